// round 1
// baseline (speedup 1.0000x reference)
#include <cuda_runtime.h>
#include <math.h>

// Problem constants
#define BB 2
#define CC 128
#define NN 8192
#define KK 16
#define TWO_PI 6.283185307179586f
#define RSQRT_C 0.08838834764831845f   // 1/sqrt(128)

// ---------------- device scratch (no allocations allowed) ----------------
__device__ float g_xsT[BB * NN * CC];     // xs transposed to [B][N][C]
__device__ float g_outT[BB * NN * CC];    // output in [B][N][C]
__device__ float g_Pt[CC * CC];           // Pt[i*128+c] = P[c][i],  P = Wk^T Wq
__device__ float g_p0[CC];                // Wk^T bq
__device__ float g_Pqt[CC * 32];          // Pqt[i*32+j] = Pq[j][i], Pq = W2 P
__device__ float g_pq0[32];               // W2 p0
__device__ float g_Wcat[160 * CC];        // rows 0..127: Wfuse^T (Wcat[i*128+o]=Wfuse[o][i]=(WoWv)[o][i])
                                          // rows 128..159: W3^T (Wcat[(128+j)*128+o]=W3[o][j]=(WoWvW2^T)[o][j])
__device__ float g_b3[CC];                // Wfuse@b2 + Wo@bv + bo
__device__ int   g_idx64;                 // 1 if idx buffer is int64, 0 if int32

// ---------------- idx dtype detection ----------------
__global__ void detect_idx_kernel(const int* __restrict__ idx32) {
    __shared__ int any;
    if (threadIdx.x == 0) any = 0;
    __syncthreads();
    int local = 0;
    for (int i = threadIdx.x; i < 2048; i += blockDim.x) {
        if (idx32[2 * i + 1] != 0) local = 1;   // high word nonzero -> int32 data
    }
    if (local) atomicOr(&any, 1);
    __syncthreads();
    if (threadIdx.x == 0) g_idx64 = (any ? 0 : 1);
}

// ---------------- weight fusion: stage 1 ----------------
// grid 128 (i), block 128 (t)
__global__ void prep1_kernel(const float* __restrict__ Wq, const float* __restrict__ Wk,
                             const float* __restrict__ Wv, const float* __restrict__ Wo,
                             const float* __restrict__ bq) {
    int i = blockIdx.x, t = threadIdx.x;
    float a = 0.f, w = 0.f;
    for (int o = 0; o < 128; ++o) {
        a += Wk[o * 128 + t] * Wq[o * 128 + i];   // P[t][i]
        w += Wo[t * 128 + o] * Wv[o * 128 + i];   // Wfuse[t][i]
    }
    g_Pt[i * 128 + t] = a;
    g_Wcat[i * 128 + t] = w;
    if (i == 0) {
        float p = 0.f;
        for (int o = 0; o < 128; ++o) p += Wk[o * 128 + t] * bq[o];
        g_p0[t] = p;
    }
}

// ---------------- weight fusion: stage 2 (depends on stage 1) ----------------
// grid 128 (i), block 128 (t)
__global__ void prep2_kernel(const float* __restrict__ W2, const float* __restrict__ Wo,
                             const float* __restrict__ b2, const float* __restrict__ bv,
                             const float* __restrict__ bo) {
    int i = blockIdx.x, t = threadIdx.x;
    if (t < 32) {
        float a = 0.f;
        for (int c = 0; c < 128; ++c) a += W2[t * 128 + c] * g_Pt[i * 128 + c];
        g_Pqt[i * 32 + t] = a;                 // Pq[t][i]
    }
    if (i < 32) {
        // W3[o=t][j=i] = sum_ii Wfuse[t][ii] * W2[i][ii]
        float a = 0.f;
        for (int ii = 0; ii < 128; ++ii) a += g_Wcat[ii * 128 + t] * W2[i * 128 + ii];
        g_Wcat[(128 + i) * 128 + t] = a;
    }
    if (i == 0) {
        if (t < 32) {
            float a = 0.f;
            for (int c = 0; c < 128; ++c) a += W2[t * 128 + c] * g_p0[c];
            g_pq0[t] = a;
        }
        float a = 0.f;
        for (int ii = 0; ii < 128; ++ii) a += g_Wcat[ii * 128 + t] * b2[ii];
        for (int c = 0; c < 128; ++c)   a += Wo[t * 128 + c] * bv[c];
        g_b3[t] = a + bo[t];
    }
}

// ---------------- transposes ----------------
// in: [B][C][N] -> out: [B][N][C]; grid (N/32, C/32, B), block (32,8)
__global__ void transpose_CN_to_NC(const float* __restrict__ in, float* __restrict__ out) {
    __shared__ float tile[32][33];
    int b = blockIdx.z;
    int n0 = blockIdx.x * 32, c0 = blockIdx.y * 32;
    int tx = threadIdx.x, ty = threadIdx.y;
    for (int r = ty; r < 32; r += 8)
        tile[r][tx] = in[((size_t)b * CC + (c0 + r)) * NN + n0 + tx];
    __syncthreads();
    for (int r = ty; r < 32; r += 8)
        out[((size_t)b * NN + (n0 + r)) * CC + c0 + tx] = tile[tx][r];
}

// in: [B][N][C] -> out: [B][C][N]
__global__ void transpose_NC_to_CN(const float* __restrict__ in, float* __restrict__ out) {
    __shared__ float tile[32][33];
    int b = blockIdx.z;
    int n0 = blockIdx.x * 32, c0 = blockIdx.y * 32;
    int tx = threadIdx.x, ty = threadIdx.y;
    for (int r = ty; r < 32; r += 8)
        tile[r][tx] = in[((size_t)b * NN + (n0 + r)) * CC + c0 + tx];
    __syncthreads();
    for (int r = ty; r < 32; r += 8)
        out[((size_t)b * CC + (c0 + r)) * NN + n0 + tx] = tile[tx][r];
}

// ---------------- main fused kernel: one block per (b, n) ----------------
__global__ __launch_bounds__(128) void lsga_main_kernel(
    const float* __restrict__ coords, const void* __restrict__ idxp,
    const float* __restrict__ Bg, const float* __restrict__ W1,
    const float* __restrict__ b1) {

    const int t = threadIdx.x;
    const int bid = blockIdx.x;
    const int b = bid >> 13;          // / 8192
    const int n = bid & (NN - 1);
    const size_t base_bn = (size_t)b * NN + n;

    __shared__ float s_x[128];
    __shared__ float s_Qp[128];
    __shared__ float s_Qpp[32];
    __shared__ int   s_idx[16];
    __shared__ float s_dp[16][4];
    __shared__ float s_Bg[256];
    __shared__ float s_sin[16][65];
    __shared__ float s_cos[16][65];
    __shared__ float s_W1t[32][129];
    __shared__ float s_nbf[16][128];
    __shared__ float s_part[4][16][32];
    __shared__ float s_rh[16][32];
    __shared__ float s_red[4][128];
    __shared__ float s_logit[16];
    __shared__ float s_attn[16];
    __shared__ float s_v[160];
    __shared__ float s_ctr[4];

    // ---- phase 0: load per-point data + block-invariant small weights ----
    s_x[t] = g_xsT[base_bn * 128 + t];
    s_Bg[t] = Bg[t];
    s_Bg[t + 128] = Bg[t + 128];
    {
        int j = t & 31;
        for (int d = (t >> 5); d < 128; d += 4)
            s_W1t[j][d] = W1[d * 32 + j];
    }
    if (t < 16) {
        long long v;
        if (g_idx64) v = ((const long long*)idxp)[base_bn * 16 + t];
        else         v = (long long)((const int*)idxp)[base_bn * 16 + t];
        s_idx[t] = (int)v;
    }
    if (t < 4) s_ctr[t] = coords[base_bn * 4 + t];
    __syncthreads();

    // ---- phase 1: gather neighbor features/coords + Q' partials ----
    #pragma unroll
    for (int k = 0; k < 16; ++k) {
        size_t m = (size_t)b * NN + s_idx[k];
        s_nbf[k][t] = g_xsT[m * 128 + t];
    }
    if (t < 64) {
        int k = t >> 2, a = t & 3;
        size_t m = (size_t)b * NN + s_idx[k];
        s_dp[k][a] = coords[m * 4 + a] - s_ctr[a];
    }
    {
        const int w = t >> 5, l = t & 31;
        float4 acc = make_float4(0.f, 0.f, 0.f, 0.f);
        const float4* Pt4 = reinterpret_cast<const float4*>(g_Pt);
        #pragma unroll 8
        for (int ii = 0; ii < 32; ++ii) {
            int i = (w << 5) + ii;
            float xv = s_x[i];
            float4 wv = Pt4[i * 32 + l];
            acc.x = fmaf(wv.x, xv, acc.x);
            acc.y = fmaf(wv.y, xv, acc.y);
            acc.z = fmaf(wv.z, xv, acc.z);
            acc.w = fmaf(wv.w, xv, acc.w);
        }
        s_red[w][4 * l + 0] = acc.x;
        s_red[w][4 * l + 1] = acc.y;
        s_red[w][4 * l + 2] = acc.z;
        s_red[w][4 * l + 3] = acc.w;
    }
    __syncthreads();

    // ---- phase 2: Q' reduce, Fourier proj + sincos, Q'' ----
    s_Qp[t] = g_p0[t] + s_red[0][t] + s_red[1][t] + s_red[2][t] + s_red[3][t];
    #pragma unroll
    for (int r = 0; r < 8; ++r) {
        int item = t + (r << 7);           // 0..1023
        int k = item >> 6, d = item & 63;
        float p = s_dp[k][0] * s_Bg[d]
                + s_dp[k][1] * s_Bg[64 + d]
                + s_dp[k][2] * s_Bg[128 + d]
                + s_dp[k][3] * s_Bg[192 + d];
        float sv, cv;
        sincosf(TWO_PI * p, &sv, &cv);
        s_sin[k][d] = sv;
        s_cos[k][d] = cv;
    }
    if (t < 32) {
        float a = 0.f;
        #pragma unroll 8
        for (int i = 0; i < 128; ++i) a = fmaf(g_Pqt[i * 32 + t], s_x[i], a);
        s_Qpp[t] = g_pq0[t] + a;
    }
    __syncthreads();

    // ---- phase 3: hidden MLP  rh[k][j] = relu(sum_d sin*W1a + cos*W1b + b1) ----
    {
        const int kt = t & 3, jt = (t >> 2) & 7, dg = t >> 5;
        float acc[4][4] = {};
        #pragma unroll 4
        for (int dd = 0; dd < 16; ++dd) {
            int d = dg * 16 + dd;
            float sk[4], ck[4];
            #pragma unroll
            for (int ki = 0; ki < 4; ++ki) {
                sk[ki] = s_sin[4 * kt + ki][d];
                ck[ki] = s_cos[4 * kt + ki][d];
            }
            #pragma unroll
            for (int jj = 0; jj < 4; ++jj) {
                float ws = s_W1t[4 * jt + jj][d];
                float wc = s_W1t[4 * jt + jj][64 + d];
                #pragma unroll
                for (int ki = 0; ki < 4; ++ki)
                    acc[ki][jj] = fmaf(sk[ki], ws, fmaf(ck[ki], wc, acc[ki][jj]));
            }
        }
        #pragma unroll
        for (int ki = 0; ki < 4; ++ki)
            #pragma unroll
            for (int jj = 0; jj < 4; ++jj)
                s_part[dg][4 * kt + ki][4 * jt + jj] = acc[ki][jj];
    }
    __syncthreads();
    #pragma unroll
    for (int it = t; it < 512; it += 128) {
        int k = it >> 5, j = it & 31;
        float h = b1[j] + s_part[0][k][j] + s_part[1][k][j] + s_part[2][k][j] + s_part[3][k][j];
        s_rh[k][j] = fmaxf(h, 0.f);
    }
    __syncthreads();

    // ---- phase 4: logits  (Q'.nbf_k + rh_k.Q'') / sqrt(C) ----
    {
        const int w = t >> 5, l = t & 31;
        #pragma unroll
        for (int kk = 0; kk < 4; ++kk) {
            int k = 4 * w + kk;
            float p = s_Qp[l]      * s_nbf[k][l]
                    + s_Qp[l + 32] * s_nbf[k][l + 32]
                    + s_Qp[l + 64] * s_nbf[k][l + 64]
                    + s_Qp[l + 96] * s_nbf[k][l + 96]
                    + s_rh[k][l]   * s_Qpp[l];
            #pragma unroll
            for (int off = 16; off; off >>= 1)
                p += __shfl_xor_sync(0xffffffffu, p, off);
            if (l == 0) s_logit[k] = p * RSQRT_C;
        }
    }
    __syncthreads();

    // ---- phase 5: softmax weights (unnormalized exp; normalize at aggregate) ----
    if (t < 16) {
        float mx = -1e30f;
        #pragma unroll
        for (int k = 0; k < 16; ++k) mx = fmaxf(mx, s_logit[k]);
        s_attn[t] = expf(s_logit[t] - mx);
    }
    __syncthreads();

    float den = 0.f;
    #pragma unroll
    for (int k = 0; k < 16; ++k) den += s_attn[k];
    float rden = 1.0f / den;

    // ---- phase 6: attention-weighted aggregates ----
    {
        float fa = 0.f;
        #pragma unroll
        for (int k = 0; k < 16; ++k) fa = fmaf(s_attn[k], s_nbf[k][t], fa);
        s_v[t] = fa * rden;
    }
    if (t < 32) {
        float ha = 0.f;
        #pragma unroll
        for (int k = 0; k < 16; ++k) ha = fmaf(s_attn[k], s_rh[k][t], ha);
        s_v[128 + t] = ha * rden;
    }
    __syncthreads();

    // ---- phase 7: fused output matvec  out = Wcat^T @ s_v + b3 ----
    {
        const int w = t >> 5, l = t & 31;
        float4 acc = make_float4(0.f, 0.f, 0.f, 0.f);
        const float4* Wc4 = reinterpret_cast<const float4*>(g_Wcat);
        #pragma unroll 8
        for (int ii = 0; ii < 40; ++ii) {
            int i = w * 40 + ii;
            float xv = s_v[i];
            float4 wv = Wc4[i * 32 + l];
            acc.x = fmaf(wv.x, xv, acc.x);
            acc.y = fmaf(wv.y, xv, acc.y);
            acc.z = fmaf(wv.z, xv, acc.z);
            acc.w = fmaf(wv.w, xv, acc.w);
        }
        s_red[w][4 * l + 0] = acc.x;
        s_red[w][4 * l + 1] = acc.y;
        s_red[w][4 * l + 2] = acc.z;
        s_red[w][4 * l + 3] = acc.w;
    }
    __syncthreads();
    g_outT[base_bn * 128 + t] =
        g_b3[t] + s_red[0][t] + s_red[1][t] + s_red[2][t] + s_red[3][t];
}

// ---------------- launch ----------------
extern "C" void kernel_launch(void* const* d_in, const int* in_sizes, int n_in,
                              void* d_out, int out_size) {
    const float* x      = (const float*)d_in[0];   // [B,C,N,1]
    const float* coords = (const float*)d_in[1];   // [B,N,4]
    const void*  idx    = d_in[2];                 // [B,N,K] int64 or int32
    const float* Bg     = (const float*)d_in[3];   // [4,64]
    const float* W1     = (const float*)d_in[4];   // [128,32]
    const float* b1     = (const float*)d_in[5];   // [32]
    const float* W2     = (const float*)d_in[6];   // [32,128]
    const float* b2     = (const float*)d_in[7];   // [128]
    const float* Wq     = (const float*)d_in[8];   // [128,128]
    const float* bq     = (const float*)d_in[9];
    const float* Wk     = (const float*)d_in[10];
    // d_in[11] = bk  (cancels in softmax)
    const float* Wv     = (const float*)d_in[12];
    const float* bv     = (const float*)d_in[13];
    const float* Wo     = (const float*)d_in[14];
    const float* bo     = (const float*)d_in[15];
    float* out = (float*)d_out;

    detect_idx_kernel<<<1, 256>>>((const int*)idx);
    prep1_kernel<<<128, 128>>>(Wq, Wk, Wv, Wo, bq);
    prep2_kernel<<<128, 128>>>(W2, Wo, b2, bv, bo);

    dim3 tgrid(NN / 32, CC / 32, BB);
    dim3 tblk(32, 8);
    float* xsT;  cudaGetSymbolAddress((void**)&xsT, g_xsT);
    float* outT; cudaGetSymbolAddress((void**)&outT, g_outT);
    transpose_CN_to_NC<<<tgrid, tblk>>>(x, xsT);

    lsga_main_kernel<<<BB * NN, 128>>>(coords, idx, Bg, W1, b1);

    transpose_NC_to_CN<<<tgrid, tblk>>>(outT, out);
}

// round 2
// speedup vs baseline: 1.5629x; 1.5629x over previous
#include <cuda_runtime.h>
#include <math.h>

#define BB 2
#define CC 128
#define NN 8192
#define KK 16
#define PTS 4
#define THREADS 256
#define TWO_PI 6.283185307179586f
#define RSQRT_C 0.08838834764831845f   // 1/sqrt(128)

// ---------------- device scratch ----------------
__device__ float g_xsT[BB * NN * CC];     // xs transposed to [B][N][C]
__device__ float g_outT[BB * NN * CC];    // output in [B][N][C]
__device__ float g_Pt[CC * CC];           // Pt[i*128+c] = P[c][i],  P = Wk^T Wq
__device__ float g_p0[CC];                // Wk^T bq
__device__ float g_Pqt[CC * 32];          // Pqt[i*32+j] = Pq[j][i], Pq = W2 P
__device__ float g_pq0[32];               // W2 p0
__device__ float g_Wcat[160 * CC];        // rows 0..127: (WoWv)^T ; rows 128..159: (WoWvW2^T)^T
__device__ float g_b3[CC];                // fused output bias
__device__ float g_W1c[CC * 32];          // [dq 0..31][j 0..31][di 0..3]: = W1[(dq*4+di)*32+j]
__device__ int   g_idx64;

// ---------------- idx dtype detection ----------------
__global__ void detect_idx_kernel(const int* __restrict__ idx32) {
    __shared__ int any;
    if (threadIdx.x == 0) any = 0;
    __syncthreads();
    int local = 0;
    for (int i = threadIdx.x; i < 2048; i += blockDim.x)
        if (idx32[2 * i + 1] != 0) local = 1;
    if (local) atomicOr(&any, 1);
    __syncthreads();
    if (threadIdx.x == 0) g_idx64 = (any ? 0 : 1);
}

// ---------------- weight fusion ----------------
__global__ void prep1_kernel(const float* __restrict__ Wq, const float* __restrict__ Wk,
                             const float* __restrict__ Wv, const float* __restrict__ Wo,
                             const float* __restrict__ bq) {
    int i = blockIdx.x, t = threadIdx.x;
    float a = 0.f, w = 0.f;
    for (int o = 0; o < 128; ++o) {
        a += Wk[o * 128 + t] * Wq[o * 128 + i];   // P[t][i]
        w += Wo[t * 128 + o] * Wv[o * 128 + i];   // Wfuse[t][i]
    }
    g_Pt[i * 128 + t] = a;
    g_Wcat[i * 128 + t] = w;
    if (i == 0) {
        float p = 0.f;
        for (int o = 0; o < 128; ++o) p += Wk[o * 128 + t] * bq[o];
        g_p0[t] = p;
    }
}

__global__ void prep2_kernel(const float* __restrict__ W2, const float* __restrict__ Wo,
                             const float* __restrict__ b2, const float* __restrict__ bv,
                             const float* __restrict__ bo) {
    int i = blockIdx.x, t = threadIdx.x;
    if (t < 32) {
        float a = 0.f;
        for (int c = 0; c < 128; ++c) a += W2[t * 128 + c] * g_Pt[i * 128 + c];
        g_Pqt[i * 32 + t] = a;
    }
    if (i < 32) {
        float a = 0.f;
        for (int ii = 0; ii < 128; ++ii) a += g_Wcat[ii * 128 + t] * W2[i * 128 + ii];
        g_Wcat[(128 + i) * 128 + t] = a;
    }
    if (i == 0) {
        if (t < 32) {
            float a = 0.f;
            for (int c = 0; c < 128; ++c) a += W2[t * 128 + c] * g_p0[c];
            g_pq0[t] = a;
        }
        float a = 0.f;
        for (int ii = 0; ii < 128; ++ii) a += g_Wcat[ii * 128 + t] * b2[ii];
        for (int c = 0; c < 128; ++c)   a += Wo[t * 128 + c] * bv[c];
        g_b3[t] = a + bo[t];
    }
}

__global__ void prep_w1_kernel(const float* __restrict__ W1) {
    int t = threadIdx.x + blockIdx.x * blockDim.x;   // 0..4095
    if (t < 4096) {
        int di = t & 3, j = (t >> 2) & 31, dq = t >> 7;
        g_W1c[(dq * 32 + j) * 4 + di] = W1[(dq * 4 + di) * 32 + j];
    }
}

// ---------------- transposes ----------------
__global__ void transpose_CN_to_NC(const float* __restrict__ in, float* __restrict__ out) {
    __shared__ float tile[32][33];
    int b = blockIdx.z;
    int n0 = blockIdx.x * 32, c0 = blockIdx.y * 32;
    int tx = threadIdx.x, ty = threadIdx.y;
    for (int r = ty; r < 32; r += 8)
        tile[r][tx] = in[((size_t)b * CC + (c0 + r)) * NN + n0 + tx];
    __syncthreads();
    for (int r = ty; r < 32; r += 8)
        out[((size_t)b * NN + (n0 + r)) * CC + c0 + tx] = tile[tx][r];
}

__global__ void transpose_NC_to_CN(const float* __restrict__ in, float* __restrict__ out) {
    __shared__ float tile[32][33];
    int b = blockIdx.z;
    int n0 = blockIdx.x * 32, c0 = blockIdx.y * 32;
    int tx = threadIdx.x, ty = threadIdx.y;
    for (int r = ty; r < 32; r += 8)
        tile[r][tx] = in[((size_t)b * NN + (n0 + r)) * CC + c0 + tx];
    __syncthreads();
    for (int r = ty; r < 32; r += 8)
        out[((size_t)b * CC + (c0 + r)) * NN + n0 + tx] = tile[tx][r];
}

// ---------------- shared memory layout ----------------
struct __align__(16) SM {
    float E[64 * 132];     // sin/cos embedding, row r = p*16+k, padded stride 132
    float nbf[64 * 128];   // gathered neighbor features
    float part[4096];      // Q'/out partials [8][4][128]  |  MLP partials [2][64][32]
    float rh[64 * 33];     // relu hidden, padded stride 33
    float x[4][128];
    float Qp[4][128];
    float Qpp[4][32];
    float v[4 * 160];
    float dp[64][4];
    float Bg[256];
    float qre[512];        // Qpp partials [4][4][32]
    float logit[64];
    float attn[64];
    float rden[4];
    float ctr[4][4];
    int   idx[64];
};

// ---------------- main fused kernel: 4 points per block ----------------
__global__ __launch_bounds__(THREADS) void lsga_main_kernel(
    const float* __restrict__ coords, const void* __restrict__ idxp,
    const float* __restrict__ Bg, const float* __restrict__ b1) {

    extern __shared__ char smem_raw[];
    SM* sm = reinterpret_cast<SM*>(smem_raw);

    const int t = threadIdx.x;
    const int g0 = blockIdx.x * PTS;
    const int b = g0 >> 13;
    const int n0 = g0 & (NN - 1);
    const size_t base = (size_t)b * NN + n0;

    // ---- P0: per-point loads ----
    #pragma unroll
    for (int m = 0; m < 2; ++m) {
        int i = (m << 8) + t;
        int p = i >> 7, c = i & 127;
        sm->x[p][c] = g_xsT[(base + p) * 128 + c];
    }
    sm->Bg[t] = Bg[t];
    if (t < 64) {
        long long v;
        if (g_idx64) v = ((const long long*)idxp)[base * 16 + t];
        else         v = (long long)((const int*)idxp)[base * 16 + t];
        sm->idx[t] = (int)v;
    }
    if (t < 16) {
        int p = t >> 2, a = t & 3;
        sm->ctr[p][a] = coords[(base + p) * 4 + a];
    }
    __syncthreads();

    // ---- P1: neighbor gathers, delta-p, Q' partials ----
    {
        // delta_p: one element per thread (64 rows x 4 comps = 256)
        int r = t >> 2, a = t & 3, p = t >> 6;
        sm->dp[r][a] = coords[((size_t)b * NN + sm->idx[r]) * 4 + a] - sm->ctr[p][a];
    }
    #pragma unroll
    for (int m = 0; m < 8; ++m) {
        int i = (m << 8) + t;           // 0..2047 float4 slots
        int r = i >> 5, q = i & 31;
        const float4* src = (const float4*)&g_xsT[((size_t)b * NN + sm->idx[r]) * 128];
        ((float4*)sm->nbf)[r * 32 + q] = __ldg(src + q);
    }
    {
        // Q' partials: warp w covers i in [16w,16w+16), lane l covers cols 4l..4l+3
        const int l = t & 31, w = t >> 5;
        float4 acc[4];
        #pragma unroll
        for (int p = 0; p < 4; ++p) acc[p] = make_float4(0.f, 0.f, 0.f, 0.f);
        const float4* Pt4 = (const float4*)g_Pt;
        #pragma unroll
        for (int ii = 0; ii < 16; ++ii) {
            int i = (w << 4) + ii;
            float4 wv = __ldg(&Pt4[i * 32 + l]);
            #pragma unroll
            for (int p = 0; p < 4; ++p) {
                float xv = sm->x[p][i];
                acc[p].x = fmaf(wv.x, xv, acc[p].x);
                acc[p].y = fmaf(wv.y, xv, acc[p].y);
                acc[p].z = fmaf(wv.z, xv, acc[p].z);
                acc[p].w = fmaf(wv.w, xv, acc[p].w);
            }
        }
        #pragma unroll
        for (int p = 0; p < 4; ++p)
            ((float4*)sm->part)[((w << 2) + p) * 32 + l] = acc[p];
    }
    __syncthreads();

    // ---- P2: Qp reduce, Fourier sincos, Qpp partials ----
    #pragma unroll
    for (int m = 0; m < 2; ++m) {
        int i = (m << 8) + t;
        int p = i >> 7, c = i & 127;
        float s = __ldg(&g_p0[c]);
        #pragma unroll
        for (int w = 0; w < 8; ++w) s += sm->part[((w << 2) + p) * 128 + c];
        sm->Qp[p][c] = s;
    }
    #pragma unroll
    for (int m = 0; m < 16; ++m) {
        int item = (m << 8) + t;        // 0..4095
        int r = item >> 6, d = item & 63;
        float pr = sm->dp[r][0] * sm->Bg[d]
                 + sm->dp[r][1] * sm->Bg[64 + d]
                 + sm->dp[r][2] * sm->Bg[128 + d]
                 + sm->dp[r][3] * sm->Bg[192 + d];
        float sv, cv;
        __sincosf(TWO_PI * pr, &sv, &cv);
        sm->E[r * 132 + d] = sv;
        sm->E[r * 132 + 64 + d] = cv;
    }
    if (t < 128) {
        int j = t & 31, ig = t >> 5;
        float a0 = 0.f, a1 = 0.f, a2 = 0.f, a3 = 0.f;
        #pragma unroll
        for (int ii = 0; ii < 32; ++ii) {
            int i = (ig << 5) + ii;
            float wv = __ldg(&g_Pqt[i * 32 + j]);
            a0 = fmaf(wv, sm->x[0][i], a0);
            a1 = fmaf(wv, sm->x[1][i], a1);
            a2 = fmaf(wv, sm->x[2][i], a2);
            a3 = fmaf(wv, sm->x[3][i], a3);
        }
        sm->qre[(ig * 4 + 0) * 32 + j] = a0;
        sm->qre[(ig * 4 + 1) * 32 + j] = a1;
        sm->qre[(ig * 4 + 2) * 32 + j] = a2;
        sm->qre[(ig * 4 + 3) * 32 + j] = a3;
    }
    __syncthreads();

    // ---- P3: Qpp reduce + hidden-MLP GEMM (64 rows x 32 j x 128 d) ----
    if (t < 128) {
        int p = t >> 5, j = t & 31;
        float s = __ldg(&g_pq0[j]);
        #pragma unroll
        for (int ig = 0; ig < 4; ++ig) s += sm->qre[(ig * 4 + p) * 32 + j];
        sm->Qpp[p][j] = s;
    }
    {
        const int dh = t >> 7;             // d-half 0/1
        const int rowg = (t >> 3) & 15;    // 16 row-groups (rows rowg+16*ri)
        const int jg = t & 7;              // 8 j-groups (j = 4jg+ji)
        float acc[4][4] = {};
        const float4* E4 = (const float4*)sm->E;     // row stride 33 float4
        const float4* W4 = (const float4*)g_W1c;
        #pragma unroll
        for (int q = 0; q < 16; ++q) {
            int dq = (dh << 4) + q;
            float4 a0 = E4[(rowg +  0) * 33 + dq];
            float4 a1 = E4[(rowg + 16) * 33 + dq];
            float4 a2 = E4[(rowg + 32) * 33 + dq];
            float4 a3 = E4[(rowg + 48) * 33 + dq];
            float4 b0 = __ldg(&W4[dq * 32 + (jg << 2) + 0]);
            float4 b1v = __ldg(&W4[dq * 32 + (jg << 2) + 1]);
            float4 b2 = __ldg(&W4[dq * 32 + (jg << 2) + 2]);
            float4 b3v = __ldg(&W4[dq * 32 + (jg << 2) + 3]);
            float4 ar[4] = {a0, a1, a2, a3};
            float4 br[4] = {b0, b1v, b2, b3v};
            #pragma unroll
            for (int ri = 0; ri < 4; ++ri)
                #pragma unroll
                for (int ji = 0; ji < 4; ++ji) {
                    acc[ri][ji] = fmaf(ar[ri].x, br[ji].x, acc[ri][ji]);
                    acc[ri][ji] = fmaf(ar[ri].y, br[ji].y, acc[ri][ji]);
                    acc[ri][ji] = fmaf(ar[ri].z, br[ji].z, acc[ri][ji]);
                    acc[ri][ji] = fmaf(ar[ri].w, br[ji].w, acc[ri][ji]);
                }
        }
        #pragma unroll
        for (int ri = 0; ri < 4; ++ri)
            #pragma unroll
            for (int ji = 0; ji < 4; ++ji)
                sm->part[dh * 2048 + (rowg + (ri << 4)) * 32 + (jg << 2) + ji] = acc[ri][ji];
    }
    __syncthreads();

    // ---- P4: relu hidden combine ----
    #pragma unroll
    for (int m = 0; m < 8; ++m) {
        int i = (m << 8) + t;              // 0..2047
        int r = i >> 5, j = i & 31;
        float h = __ldg(&b1[j]) + sm->part[r * 32 + j] + sm->part[2048 + r * 32 + j];
        sm->rh[r * 33 + j] = fmaxf(h, 0.f);
    }
    __syncthreads();

    // ---- P5: logits ----
    {
        const int l = t & 31, w = t >> 5;
        #pragma unroll
        for (int rr = 0; rr < 8; ++rr) {
            int r = (w << 3) + rr;
            int p = r >> 4;
            float val = sm->Qp[p][l]      * sm->nbf[r * 128 + l]
                      + sm->Qp[p][l + 32] * sm->nbf[r * 128 + l + 32]
                      + sm->Qp[p][l + 64] * sm->nbf[r * 128 + l + 64]
                      + sm->Qp[p][l + 96] * sm->nbf[r * 128 + l + 96]
                      + sm->rh[r * 33 + l] * sm->Qpp[p][l];
            #pragma unroll
            for (int off = 16; off; off >>= 1)
                val += __shfl_xor_sync(0xffffffffu, val, off);
            if (l == 0) sm->logit[r] = val * RSQRT_C;
        }
    }
    __syncthreads();

    // ---- P6: softmax (per point, 16-lane subgroups) ----
    if (t < 64) {
        int p = t >> 4, k = t & 15;
        float lg = sm->logit[t];
        float mx = lg;
        #pragma unroll
        for (int off = 8; off; off >>= 1)
            mx = fmaxf(mx, __shfl_xor_sync(0xffffffffu, mx, off));
        float e = __expf(lg - mx);
        float s = e;
        #pragma unroll
        for (int off = 8; off; off >>= 1)
            s += __shfl_xor_sync(0xffffffffu, s, off);
        sm->attn[t] = e;
        if (k == 0) sm->rden[p] = 1.0f / s;
    }
    __syncthreads();

    // ---- P7: attention-weighted aggregates ----
    #pragma unroll
    for (int m = 0; m < 2; ++m) {
        int i = (m << 8) + t;
        int p = i >> 7, c = i & 127;
        float fa = 0.f;
        #pragma unroll
        for (int k = 0; k < 16; ++k)
            fa = fmaf(sm->attn[p * 16 + k], sm->nbf[(p * 16 + k) * 128 + c], fa);
        sm->v[p * 160 + c] = fa * sm->rden[p];
    }
    if (t < 128) {
        int p = t >> 5, j = t & 31;
        float ha = 0.f;
        #pragma unroll
        for (int k = 0; k < 16; ++k)
            ha = fmaf(sm->attn[p * 16 + k], sm->rh[(p * 16 + k) * 33 + j], ha);
        sm->v[p * 160 + 128 + j] = ha * sm->rden[p];
    }
    __syncthreads();

    // ---- P8: fused output matvec partials (160 -> 128) ----
    {
        const int l = t & 31, w = t >> 5;
        float4 acc[4];
        #pragma unroll
        for (int p = 0; p < 4; ++p) acc[p] = make_float4(0.f, 0.f, 0.f, 0.f);
        const float4* Wc4 = (const float4*)g_Wcat;
        #pragma unroll
        for (int ii = 0; ii < 20; ++ii) {
            int i = w * 20 + ii;
            float4 wv = __ldg(&Wc4[i * 32 + l]);
            #pragma unroll
            for (int p = 0; p < 4; ++p) {
                float xv = sm->v[p * 160 + i];
                acc[p].x = fmaf(wv.x, xv, acc[p].x);
                acc[p].y = fmaf(wv.y, xv, acc[p].y);
                acc[p].z = fmaf(wv.z, xv, acc[p].z);
                acc[p].w = fmaf(wv.w, xv, acc[p].w);
            }
        }
        #pragma unroll
        for (int p = 0; p < 4; ++p)
            ((float4*)sm->part)[((w << 2) + p) * 32 + l] = acc[p];
    }
    __syncthreads();

    // ---- P9: output reduce + store ----
    #pragma unroll
    for (int m = 0; m < 2; ++m) {
        int i = (m << 8) + t;
        int p = i >> 7, c = i & 127;
        float o = __ldg(&g_b3[c]);
        #pragma unroll
        for (int w = 0; w < 8; ++w) o += sm->part[((w << 2) + p) * 128 + c];
        g_outT[(base + p) * 128 + c] = o;
    }
}

// ---------------- launch ----------------
extern "C" void kernel_launch(void* const* d_in, const int* in_sizes, int n_in,
                              void* d_out, int out_size) {
    const float* x      = (const float*)d_in[0];
    const float* coords = (const float*)d_in[1];
    const void*  idx    = d_in[2];
    const float* Bg     = (const float*)d_in[3];
    const float* W1     = (const float*)d_in[4];
    const float* b1     = (const float*)d_in[5];
    const float* W2     = (const float*)d_in[6];
    const float* b2     = (const float*)d_in[7];
    const float* Wq     = (const float*)d_in[8];
    const float* bq     = (const float*)d_in[9];
    const float* Wk     = (const float*)d_in[10];
    const float* Wv     = (const float*)d_in[12];
    const float* bv     = (const float*)d_in[13];
    const float* Wo     = (const float*)d_in[14];
    const float* bo     = (const float*)d_in[15];
    float* out = (float*)d_out;

    static bool attr_set = false;
    if (!attr_set) {
        cudaFuncSetAttribute(lsga_main_kernel,
                             cudaFuncAttributeMaxDynamicSharedMemorySize,
                             (int)sizeof(SM));
        attr_set = true;
    }

    detect_idx_kernel<<<1, 256>>>((const int*)idx);
    prep1_kernel<<<128, 128>>>(Wq, Wk, Wv, Wo, bq);
    prep2_kernel<<<128, 128>>>(W2, Wo, b2, bv, bo);
    prep_w1_kernel<<<16, 256>>>(W1);

    dim3 tgrid(NN / 32, CC / 32, BB);
    dim3 tblk(32, 8);
    float* xsT;  cudaGetSymbolAddress((void**)&xsT, g_xsT);
    float* outT; cudaGetSymbolAddress((void**)&outT, g_outT);
    transpose_CN_to_NC<<<tgrid, tblk>>>(x, xsT);

    lsga_main_kernel<<<(BB * NN) / PTS, THREADS, sizeof(SM)>>>(coords, idx, Bg, b1);

    transpose_NC_to_CN<<<tgrid, tblk>>>(outT, out);
}

// round 3
// speedup vs baseline: 1.5742x; 1.0072x over previous
#include <cuda_runtime.h>
#include <math.h>

#define BB 2
#define CC 128
#define NN 8192
#define PTS 4
#define THREADS 256
#define TWO_PI 6.283185307179586f
#define RSQRT_C 0.08838834764831845f   // 1/sqrt(128)

// ---------------- device scratch ----------------
__device__ float g_xsT[BB * NN * CC];     // xs transposed to [B][N][C]
__device__ float g_Qp [BB * NN * CC];     // Q' per point [n][c]
__device__ float g_Qpp[BB * NN * 32];     // Q'' per point [n][j]
__device__ float g_v  [BB * NN * 160];    // attention aggregates [n][160]
__device__ float g_Pt[CC * CC];           // Pt[i*128+c] = P[c][i],  P = Wk^T Wq
__device__ float g_p0[CC];                // Wk^T bq
__device__ float g_Pqt[CC * 32];          // Pqt[i*32+j] = Pq[j][i], Pq = W2 P
__device__ float g_pq0[32];               // W2 p0
__device__ float g_Wcat[160 * CC];        // rows 0..127: (WoWv)^T ; rows 128..159: (WoWvW2^T)^T
__device__ float g_b3[CC];                // fused output bias
__device__ float g_W1c[CC * 32];          // packed W1: [dq][j][di] = W1[(dq*4+di)*32+j]
__device__ int   g_idx64;

// ---------------- prep stage 1 (+ idx dtype detect in block 128) ----------------
__global__ void prep1_kernel(const float* __restrict__ Wq, const float* __restrict__ Wk,
                             const float* __restrict__ Wv, const float* __restrict__ Wo,
                             const float* __restrict__ bq, const int* __restrict__ idx32) {
    int i = blockIdx.x, t = threadIdx.x;
    if (i == 128) {
        __shared__ int any;
        if (t == 0) any = 0;
        __syncthreads();
        int local = 0;
        for (int e = t; e < 2048; e += 128)
            if (idx32[2 * e + 1] != 0) local = 1;
        if (local) atomicOr(&any, 1);
        __syncthreads();
        if (t == 0) g_idx64 = (any ? 0 : 1);
        return;
    }
    float a = 0.f, w = 0.f;
    for (int o = 0; o < 128; ++o) {
        a += Wk[o * 128 + t] * Wq[o * 128 + i];   // P[t][i]
        w += Wo[t * 128 + o] * Wv[o * 128 + i];   // Wfuse[t][i]
    }
    g_Pt[i * 128 + t] = a;
    g_Wcat[i * 128 + t] = w;
    if (i == 0) {
        float p = 0.f;
        for (int o = 0; o < 128; ++o) p += Wk[o * 128 + t] * bq[o];
        g_p0[t] = p;
    }
}

// ---------------- prep stage 2 (+ W1 repack) ----------------
__global__ void prep2_kernel(const float* __restrict__ W2, const float* __restrict__ Wo,
                             const float* __restrict__ b2, const float* __restrict__ bv,
                             const float* __restrict__ bo, const float* __restrict__ W1) {
    int i = blockIdx.x, t = threadIdx.x;
    if (t < 32) {
        float a = 0.f;
        for (int c = 0; c < 128; ++c) a += W2[t * 128 + c] * g_Pt[i * 128 + c];
        g_Pqt[i * 32 + t] = a;
        // W1 repack: element e = i*32 + t
        int e = i * 32 + t;
        int di = e & 3, j = (e >> 2) & 31, dq = e >> 7;
        g_W1c[(dq * 32 + j) * 4 + di] = W1[(dq * 4 + di) * 32 + j];
    }
    if (i < 32) {
        float a = 0.f;
        for (int ii = 0; ii < 128; ++ii) a += g_Wcat[ii * 128 + t] * W2[i * 128 + ii];
        g_Wcat[(128 + i) * 128 + t] = a;
    }
    if (i == 0) {
        if (t < 32) {
            float a = 0.f;
            for (int c = 0; c < 128; ++c) a += W2[t * 128 + c] * g_p0[c];
            g_pq0[t] = a;
        }
        float a = 0.f;
        for (int ii = 0; ii < 128; ++ii) a += g_Wcat[ii * 128 + t] * b2[ii];
        for (int c = 0; c < 128; ++c)   a += Wo[t * 128 + c] * bv[c];
        g_b3[t] = a + bo[t];
    }
}

// ---------------- pre kernel: transpose + Q' + Q'' GEMMs, 32 points/block ----
__global__ __launch_bounds__(256) void pre_kernel(const float* __restrict__ x) {
    __shared__ float xs[128][36];   // [i(c)][n], padded for aligned float4
    const int t = threadIdx.x;
    const int blk = blockIdx.x;
    const int b = blk >> 8;
    const int n0 = (blk & 255) << 5;
    const size_t gbase = (size_t)b * NN + n0;

    #pragma unroll
    for (int m = 0; m < 16; ++m) {
        int e = (m << 8) + t;
        int i = e >> 5, nn = e & 31;
        xs[i][nn] = x[((size_t)(b * 128 + i) << 13) + n0 + nn];
    }
    __syncthreads();

    // write transposed copy
    #pragma unroll
    for (int m = 0; m < 16; ++m) {
        int e = (m << 8) + t;
        int n = e >> 7, c = e & 127;
        g_xsT[(gbase + n) * 128 + c] = xs[c][n];
    }

    // Q' GEMM: 32n x 128c over i=128
    {
        const int cg = t & 31, ng = t >> 5;
        float4 acc0 = make_float4(0,0,0,0), acc1 = acc0, acc2 = acc0, acc3 = acc0;
        const float4* Pt4 = (const float4*)g_Pt;
        #pragma unroll 8
        for (int i = 0; i < 128; ++i) {
            float4 wv = __ldg(&Pt4[i * 32 + cg]);
            float4 xv = *(const float4*)&xs[i][ng << 2];
            acc0.x = fmaf(xv.x, wv.x, acc0.x); acc0.y = fmaf(xv.x, wv.y, acc0.y);
            acc0.z = fmaf(xv.x, wv.z, acc0.z); acc0.w = fmaf(xv.x, wv.w, acc0.w);
            acc1.x = fmaf(xv.y, wv.x, acc1.x); acc1.y = fmaf(xv.y, wv.y, acc1.y);
            acc1.z = fmaf(xv.y, wv.z, acc1.z); acc1.w = fmaf(xv.y, wv.w, acc1.w);
            acc2.x = fmaf(xv.z, wv.x, acc2.x); acc2.y = fmaf(xv.z, wv.y, acc2.y);
            acc2.z = fmaf(xv.z, wv.z, acc2.z); acc2.w = fmaf(xv.z, wv.w, acc2.w);
            acc3.x = fmaf(xv.w, wv.x, acc3.x); acc3.y = fmaf(xv.w, wv.y, acc3.y);
            acc3.z = fmaf(xv.w, wv.z, acc3.z); acc3.w = fmaf(xv.w, wv.w, acc3.w);
        }
        float4 p0v = __ldg(&((const float4*)g_p0)[cg]);
        float4 r0 = make_float4(acc0.x+p0v.x, acc0.y+p0v.y, acc0.z+p0v.z, acc0.w+p0v.w);
        float4 r1 = make_float4(acc1.x+p0v.x, acc1.y+p0v.y, acc1.z+p0v.z, acc1.w+p0v.w);
        float4 r2 = make_float4(acc2.x+p0v.x, acc2.y+p0v.y, acc2.z+p0v.z, acc2.w+p0v.w);
        float4 r3 = make_float4(acc3.x+p0v.x, acc3.y+p0v.y, acc3.z+p0v.z, acc3.w+p0v.w);
        float4* Qp4 = (float4*)g_Qp;
        Qp4[(gbase + (ng << 2) + 0) * 32 + cg] = r0;
        Qp4[(gbase + (ng << 2) + 1) * 32 + cg] = r1;
        Qp4[(gbase + (ng << 2) + 2) * 32 + cg] = r2;
        Qp4[(gbase + (ng << 2) + 3) * 32 + cg] = r3;
    }

    // Q'' GEMM: 32n x 32j over i=128
    {
        const int j = t & 31, ng = t >> 5;
        float a0 = 0.f, a1 = 0.f, a2 = 0.f, a3 = 0.f;
        #pragma unroll 8
        for (int i = 0; i < 128; ++i) {
            float w = __ldg(&g_Pqt[i * 32 + j]);
            float4 xv = *(const float4*)&xs[i][ng << 2];
            a0 = fmaf(w, xv.x, a0);
            a1 = fmaf(w, xv.y, a1);
            a2 = fmaf(w, xv.z, a2);
            a3 = fmaf(w, xv.w, a3);
        }
        float q0 = __ldg(&g_pq0[j]);
        g_Qpp[(gbase + (ng << 2) + 0) * 32 + j] = a0 + q0;
        g_Qpp[(gbase + (ng << 2) + 1) * 32 + j] = a1 + q0;
        g_Qpp[(gbase + (ng << 2) + 2) * 32 + j] = a2 + q0;
        g_Qpp[(gbase + (ng << 2) + 3) * 32 + j] = a3 + q0;
    }
}

// ---------------- shared memory layout for main ----------------
struct __align__(16) SM {
    float E[64 * 132];     // sin/cos embedding, padded stride 132
    float nbf[64 * 128];   // gathered neighbor features
    float part[4096];      // MLP partials [2][64][32]
    float rh[64 * 33];     // relu hidden, padded stride 33
    float Qp[4][128];
    float Qpp[4][32];
    float dp[64][4];
    float Bg[256];
    float logit[64];
    float attn[64];
    float rden[4];
    float ctr[4][4];
    int   idx[64];
};

// ---------------- main kernel: 4 points/block ----------------
__global__ __launch_bounds__(THREADS) void lsga_main_kernel(
    const float* __restrict__ coords, const void* __restrict__ idxp,
    const float* __restrict__ Bg, const float* __restrict__ b1) {

    extern __shared__ char smem_raw[];
    SM* sm = reinterpret_cast<SM*>(smem_raw);

    const int t = threadIdx.x;
    const int g0 = blockIdx.x * PTS;
    const int b = g0 >> 13;
    const int n0 = g0 & (NN - 1);
    const size_t base = (size_t)b * NN + n0;

    // ---- P0: loads ----
    #pragma unroll
    for (int m = 0; m < 2; ++m) {
        int e = (m << 8) + t;
        int p = e >> 7, c = e & 127;
        sm->Qp[p][c] = g_Qp[(base + p) * 128 + c];
    }
    if (t < 128) {
        int p = t >> 5, j = t & 31;
        sm->Qpp[p][j] = g_Qpp[(base + p) * 32 + j];
    }
    sm->Bg[t] = Bg[t] * TWO_PI;
    if (t < 64) {
        long long v;
        if (g_idx64) v = ((const long long*)idxp)[base * 16 + t];
        else         v = (long long)((const int*)idxp)[base * 16 + t];
        sm->idx[t] = (int)v;
    }
    if (t < 16) {
        int p = t >> 2, a = t & 3;
        sm->ctr[p][a] = coords[(base + p) * 4 + a];
    }
    __syncthreads();

    // ---- P1: delta-p + neighbor gather ----
    {
        int r = t >> 2, a = t & 3, p = t >> 6;
        sm->dp[r][a] = coords[((size_t)b * NN + sm->idx[r]) * 4 + a] - sm->ctr[p][a];
    }
    #pragma unroll
    for (int m = 0; m < 8; ++m) {
        int i = (m << 8) + t;
        int r = i >> 5, q = i & 31;
        const float4* src = (const float4*)&g_xsT[((size_t)b * NN + sm->idx[r]) * 128];
        ((float4*)sm->nbf)[r * 32 + q] = __ldg(src + q);
    }
    __syncthreads();

    // ---- P2: Fourier sincos ----
    #pragma unroll
    for (int m = 0; m < 16; ++m) {
        int item = (m << 8) + t;
        int r = item >> 6, d = item & 63;
        float pr = sm->dp[r][0] * sm->Bg[d]
                 + sm->dp[r][1] * sm->Bg[64 + d]
                 + sm->dp[r][2] * sm->Bg[128 + d]
                 + sm->dp[r][3] * sm->Bg[192 + d];
        float sv, cv;
        __sincosf(pr, &sv, &cv);
        sm->E[r * 132 + d] = sv;
        sm->E[r * 132 + 64 + d] = cv;
    }
    __syncthreads();

    // ---- P3: hidden MLP GEMM (64 rows x 32 j x 128 d) ----
    {
        const int dh = t >> 7;
        const int rowg = (t >> 3) & 15;
        const int jg = t & 7;
        float acc[4][4] = {};
        const float4* E4 = (const float4*)sm->E;    // row stride 33 float4
        const float4* W4 = (const float4*)g_W1c;
        #pragma unroll
        for (int q = 0; q < 16; ++q) {
            int dq = (dh << 4) + q;
            float4 ar[4];
            ar[0] = E4[(rowg +  0) * 33 + dq];
            ar[1] = E4[(rowg + 16) * 33 + dq];
            ar[2] = E4[(rowg + 32) * 33 + dq];
            ar[3] = E4[(rowg + 48) * 33 + dq];
            float4 br[4];
            br[0] = __ldg(&W4[dq * 32 + (jg << 2) + 0]);
            br[1] = __ldg(&W4[dq * 32 + (jg << 2) + 1]);
            br[2] = __ldg(&W4[dq * 32 + (jg << 2) + 2]);
            br[3] = __ldg(&W4[dq * 32 + (jg << 2) + 3]);
            #pragma unroll
            for (int ri = 0; ri < 4; ++ri)
                #pragma unroll
                for (int ji = 0; ji < 4; ++ji) {
                    acc[ri][ji] = fmaf(ar[ri].x, br[ji].x, acc[ri][ji]);
                    acc[ri][ji] = fmaf(ar[ri].y, br[ji].y, acc[ri][ji]);
                    acc[ri][ji] = fmaf(ar[ri].z, br[ji].z, acc[ri][ji]);
                    acc[ri][ji] = fmaf(ar[ri].w, br[ji].w, acc[ri][ji]);
                }
        }
        #pragma unroll
        for (int ri = 0; ri < 4; ++ri)
            #pragma unroll
            for (int ji = 0; ji < 4; ++ji)
                sm->part[dh * 2048 + (rowg + (ri << 4)) * 32 + (jg << 2) + ji] = acc[ri][ji];
    }
    __syncthreads();

    // ---- P4: relu hidden combine ----
    #pragma unroll
    for (int m = 0; m < 8; ++m) {
        int i = (m << 8) + t;
        int r = i >> 5, j = i & 31;
        float h = __ldg(&b1[j]) + sm->part[r * 32 + j] + sm->part[2048 + r * 32 + j];
        sm->rh[r * 33 + j] = fmaxf(h, 0.f);
    }
    __syncthreads();

    // ---- P5: logits ----
    {
        const int l = t & 31, w = t >> 5;
        #pragma unroll
        for (int rr = 0; rr < 8; ++rr) {
            int r = (w << 3) + rr;
            int p = r >> 4;
            float val = sm->Qp[p][l]      * sm->nbf[r * 128 + l]
                      + sm->Qp[p][l + 32] * sm->nbf[r * 128 + l + 32]
                      + sm->Qp[p][l + 64] * sm->nbf[r * 128 + l + 64]
                      + sm->Qp[p][l + 96] * sm->nbf[r * 128 + l + 96]
                      + sm->rh[r * 33 + l] * sm->Qpp[p][l];
            #pragma unroll
            for (int off = 16; off; off >>= 1)
                val += __shfl_xor_sync(0xffffffffu, val, off);
            if (l == 0) sm->logit[r] = val * RSQRT_C;
        }
    }
    __syncthreads();

    // ---- P6: softmax ----
    if (t < 64) {
        int p = t >> 4, k = t & 15;
        float lg = sm->logit[t];
        float mx = lg;
        #pragma unroll
        for (int off = 8; off; off >>= 1)
            mx = fmaxf(mx, __shfl_xor_sync(0xffffffffu, mx, off));
        float e = __expf(lg - mx);
        float s = e;
        #pragma unroll
        for (int off = 8; off; off >>= 1)
            s += __shfl_xor_sync(0xffffffffu, s, off);
        sm->attn[t] = e;
        if (k == 0) sm->rden[p] = 1.0f / s;
    }
    __syncthreads();

    // ---- P7: attention-weighted aggregates -> g_v ----
    #pragma unroll
    for (int m = 0; m < 2; ++m) {
        int i = (m << 8) + t;
        int p = i >> 7, c = i & 127;
        float fa = 0.f;
        #pragma unroll
        for (int k = 0; k < 16; ++k)
            fa = fmaf(sm->attn[p * 16 + k], sm->nbf[(p * 16 + k) * 128 + c], fa);
        g_v[(base + p) * 160 + c] = fa * sm->rden[p];
    }
    if (t < 128) {
        int p = t >> 5, j = t & 31;
        float ha = 0.f;
        #pragma unroll
        for (int k = 0; k < 16; ++k)
            ha = fmaf(sm->attn[p * 16 + k], sm->rh[(p * 16 + k) * 33 + j], ha);
        g_v[(base + p) * 160 + 128 + j] = ha * sm->rden[p];
    }
}

// ---------------- output GEMM + transpose: 32 points/block ----------------
__global__ __launch_bounds__(256) void out_kernel(float* __restrict__ out) {
    __shared__ float vs[160][36];
    __shared__ float os[128][33];
    const int t = threadIdx.x;
    const int blk = blockIdx.x;
    const int b = blk >> 8;
    const int n0 = (blk & 255) << 5;
    const size_t gbase = (size_t)b * NN + n0;

    #pragma unroll
    for (int m = 0; m < 20; ++m) {
        int e = (m << 8) + t;
        int n = e / 160;
        int i = e - n * 160;
        vs[i][n] = g_v[(gbase + n) * 160 + i];
    }
    __syncthreads();

    {
        const int cg = t & 31, ng = t >> 5;
        float4 acc0 = make_float4(0,0,0,0), acc1 = acc0, acc2 = acc0, acc3 = acc0;
        const float4* Wc4 = (const float4*)g_Wcat;
        #pragma unroll 8
        for (int i = 0; i < 160; ++i) {
            float4 wv = __ldg(&Wc4[i * 32 + cg]);
            float4 xv = *(const float4*)&vs[i][ng << 2];
            acc0.x = fmaf(xv.x, wv.x, acc0.x); acc0.y = fmaf(xv.x, wv.y, acc0.y);
            acc0.z = fmaf(xv.x, wv.z, acc0.z); acc0.w = fmaf(xv.x, wv.w, acc0.w);
            acc1.x = fmaf(xv.y, wv.x, acc1.x); acc1.y = fmaf(xv.y, wv.y, acc1.y);
            acc1.z = fmaf(xv.y, wv.z, acc1.z); acc1.w = fmaf(xv.y, wv.w, acc1.w);
            acc2.x = fmaf(xv.z, wv.x, acc2.x); acc2.y = fmaf(xv.z, wv.y, acc2.y);
            acc2.z = fmaf(xv.z, wv.z, acc2.z); acc2.w = fmaf(xv.z, wv.w, acc2.w);
            acc3.x = fmaf(xv.w, wv.x, acc3.x); acc3.y = fmaf(xv.w, wv.y, acc3.y);
            acc3.z = fmaf(xv.w, wv.z, acc3.z); acc3.w = fmaf(xv.w, wv.w, acc3.w);
        }
        float4 b3v = __ldg(&((const float4*)g_b3)[cg]);
        int nb = ng << 2, cb = cg << 2;
        os[cb + 0][nb + 0] = acc0.x + b3v.x; os[cb + 1][nb + 0] = acc0.y + b3v.y;
        os[cb + 2][nb + 0] = acc0.z + b3v.z; os[cb + 3][nb + 0] = acc0.w + b3v.w;
        os[cb + 0][nb + 1] = acc1.x + b3v.x; os[cb + 1][nb + 1] = acc1.y + b3v.y;
        os[cb + 2][nb + 1] = acc1.z + b3v.z; os[cb + 3][nb + 1] = acc1.w + b3v.w;
        os[cb + 0][nb + 2] = acc2.x + b3v.x; os[cb + 1][nb + 2] = acc2.y + b3v.y;
        os[cb + 2][nb + 2] = acc2.z + b3v.z; os[cb + 3][nb + 2] = acc2.w + b3v.w;
        os[cb + 0][nb + 3] = acc3.x + b3v.x; os[cb + 1][nb + 3] = acc3.y + b3v.y;
        os[cb + 2][nb + 3] = acc3.z + b3v.z; os[cb + 3][nb + 3] = acc3.w + b3v.w;
    }
    __syncthreads();

    #pragma unroll
    for (int m = 0; m < 16; ++m) {
        int e = (m << 8) + t;
        int c = e >> 5, nn = e & 31;
        out[((size_t)(b * 128 + c) << 13) + n0 + nn] = os[c][nn];
    }
}

// ---------------- launch ----------------
extern "C" void kernel_launch(void* const* d_in, const int* in_sizes, int n_in,
                              void* d_out, int out_size) {
    const float* x      = (const float*)d_in[0];
    const float* coords = (const float*)d_in[1];
    const void*  idx    = d_in[2];
    const float* Bg     = (const float*)d_in[3];
    const float* W1     = (const float*)d_in[4];
    const float* b1     = (const float*)d_in[5];
    const float* W2     = (const float*)d_in[6];
    const float* b2     = (const float*)d_in[7];
    const float* Wq     = (const float*)d_in[8];
    const float* bq     = (const float*)d_in[9];
    const float* Wk     = (const float*)d_in[10];
    const float* Wv     = (const float*)d_in[12];
    const float* bv     = (const float*)d_in[13];
    const float* Wo     = (const float*)d_in[14];
    const float* bo     = (const float*)d_in[15];
    float* out = (float*)d_out;

    static bool attr_set = false;
    if (!attr_set) {
        cudaFuncSetAttribute(lsga_main_kernel,
                             cudaFuncAttributeMaxDynamicSharedMemorySize,
                             (int)sizeof(SM));
        attr_set = true;
    }

    prep1_kernel<<<129, 128>>>(Wq, Wk, Wv, Wo, bq, (const int*)idx);
    prep2_kernel<<<128, 128>>>(W2, Wo, b2, bv, bo, W1);
    pre_kernel<<<(BB * NN) / 32, 256>>>(x);
    lsga_main_kernel<<<(BB * NN) / PTS, THREADS, sizeof(SM)>>>(coords, idx, Bg, b1);
    out_kernel<<<(BB * NN) / 32, 256>>>(out);
}

// round 4
// speedup vs baseline: 2.3043x; 1.4638x over previous
#include <cuda_runtime.h>
#include <cuda_fp16.h>
#include <math.h>
#include <stdint.h>

#define BB 2
#define CC 128
#define NN 8192
#define PTS 4
#define THREADS 256
#define TWO_PI 6.283185307179586f
#define RSQRT_C 0.08838834764831845f   // 1/sqrt(128)

// ---------------- device scratch ----------------
__device__ float g_xsT[BB * NN * CC];     // xs transposed to [B][N][C]
__device__ float g_Qp [BB * NN * CC];     // Q' per point [n][c]
__device__ float g_Qpp[BB * NN * 32];     // Q'' per point [n][j]
__device__ float g_v  [BB * NN * 160];    // attention aggregates [n][160]
__device__ float g_Pt[CC * CC];           // Pt[i*128+c] = P[c][i],  P = Wk^T Wq
__device__ float g_p0[CC];                // Wk^T bq
__device__ float g_Pqt[CC * 32];          // Pqt[i*32+j] = Pq[j][i], Pq = W2 P
__device__ float g_pq0[32];               // W2 p0
__device__ float g_Wcat[160 * CC];        // rows 0..127: (WoWv)^T ; rows 128..159: (WoWvW2^T)^T
__device__ float g_b3[CC];                // fused output bias
__device__ __half g_W1h[32 * 128];        // W1 transposed to [j][d], fp16
__device__ int   g_idx64;

// ---------------- mma helpers ----------------
__device__ __forceinline__ void ldmatrix_x4(uint32_t* a, uint32_t saddr) {
    asm volatile("ldmatrix.sync.aligned.m8n8.x4.shared.b16 {%0,%1,%2,%3}, [%4];"
                 : "=r"(a[0]), "=r"(a[1]), "=r"(a[2]), "=r"(a[3]) : "r"(saddr));
}
__device__ __forceinline__ void mma16816(float* c, const uint32_t* a, uint32_t b0, uint32_t b1) {
    asm volatile("mma.sync.aligned.m16n8k16.row.col.f32.f16.f16.f32 "
                 "{%0,%1,%2,%3}, {%4,%5,%6,%7}, {%8,%9}, {%0,%1,%2,%3};"
                 : "+f"(c[0]), "+f"(c[1]), "+f"(c[2]), "+f"(c[3])
                 : "r"(a[0]), "r"(a[1]), "r"(a[2]), "r"(a[3]), "r"(b0), "r"(b1));
}

// ---------------- prep stage 1 (+ idx dtype detect in block 128) ----------------
__global__ void prep1_kernel(const float* __restrict__ Wq, const float* __restrict__ Wk,
                             const float* __restrict__ Wv, const float* __restrict__ Wo,
                             const float* __restrict__ bq, const int* __restrict__ idx32) {
    int i = blockIdx.x, t = threadIdx.x;
    if (i == 128) {
        __shared__ int any;
        if (t == 0) any = 0;
        __syncthreads();
        int local = 0;
        for (int e = t; e < 2048; e += 128)
            if (idx32[2 * e + 1] != 0) local = 1;
        if (local) atomicOr(&any, 1);
        __syncthreads();
        if (t == 0) g_idx64 = (any ? 0 : 1);
        return;
    }
    float a = 0.f, w = 0.f;
    for (int o = 0; o < 128; ++o) {
        a += Wk[o * 128 + t] * Wq[o * 128 + i];   // P[t][i]
        w += Wo[t * 128 + o] * Wv[o * 128 + i];   // Wfuse[t][i]
    }
    g_Pt[i * 128 + t] = a;
    g_Wcat[i * 128 + t] = w;
    if (i == 0) {
        float p = 0.f;
        for (int o = 0; o < 128; ++o) p += Wk[o * 128 + t] * bq[o];
        g_p0[t] = p;
    }
}

// ---------------- prep stage 2 (+ W1 fp16 transpose) ----------------
__global__ void prep2_kernel(const float* __restrict__ W2, const float* __restrict__ Wo,
                             const float* __restrict__ b2, const float* __restrict__ bv,
                             const float* __restrict__ bo, const float* __restrict__ W1) {
    int i = blockIdx.x, t = threadIdx.x;
    if (t < 32) {
        float a = 0.f;
        for (int c = 0; c < 128; ++c) a += W2[t * 128 + c] * g_Pt[i * 128 + c];
        g_Pqt[i * 32 + t] = a;
        g_W1h[t * 128 + i] = __float2half(W1[i * 32 + t]);   // Wt[j][d]
    }
    if (i < 32) {
        float a = 0.f;
        for (int ii = 0; ii < 128; ++ii) a += g_Wcat[ii * 128 + t] * W2[i * 128 + ii];
        g_Wcat[(128 + i) * 128 + t] = a;
    }
    if (i == 0) {
        if (t < 32) {
            float a = 0.f;
            for (int c = 0; c < 128; ++c) a += W2[t * 128 + c] * g_p0[c];
            g_pq0[t] = a;
        }
        float a = 0.f;
        for (int ii = 0; ii < 128; ++ii) a += g_Wcat[ii * 128 + t] * b2[ii];
        for (int c = 0; c < 128; ++c)   a += Wo[t * 128 + c] * bv[c];
        g_b3[t] = a + bo[t];
    }
}

// ---------------- pre kernel: transpose + Q' + Q'' GEMMs, 32 points/block ----
__global__ __launch_bounds__(256) void pre_kernel(const float* __restrict__ x) {
    __shared__ float xs[128][36];
    const int t = threadIdx.x;
    const int blk = blockIdx.x;
    const int b = blk >> 8;
    const int n0 = (blk & 255) << 5;
    const size_t gbase = (size_t)b * NN + n0;

    #pragma unroll
    for (int m = 0; m < 16; ++m) {
        int e = (m << 8) + t;
        int i = e >> 5, nn = e & 31;
        xs[i][nn] = x[((size_t)(b * 128 + i) << 13) + n0 + nn];
    }
    __syncthreads();

    #pragma unroll
    for (int m = 0; m < 16; ++m) {
        int e = (m << 8) + t;
        int n = e >> 7, c = e & 127;
        g_xsT[(gbase + n) * 128 + c] = xs[c][n];
    }

    {
        const int cg = t & 31, ng = t >> 5;
        float4 acc0 = make_float4(0,0,0,0), acc1 = acc0, acc2 = acc0, acc3 = acc0;
        const float4* Pt4 = (const float4*)g_Pt;
        #pragma unroll 8
        for (int i = 0; i < 128; ++i) {
            float4 wv = __ldg(&Pt4[i * 32 + cg]);
            float4 xv = *(const float4*)&xs[i][ng << 2];
            acc0.x = fmaf(xv.x, wv.x, acc0.x); acc0.y = fmaf(xv.x, wv.y, acc0.y);
            acc0.z = fmaf(xv.x, wv.z, acc0.z); acc0.w = fmaf(xv.x, wv.w, acc0.w);
            acc1.x = fmaf(xv.y, wv.x, acc1.x); acc1.y = fmaf(xv.y, wv.y, acc1.y);
            acc1.z = fmaf(xv.y, wv.z, acc1.z); acc1.w = fmaf(xv.y, wv.w, acc1.w);
            acc2.x = fmaf(xv.z, wv.x, acc2.x); acc2.y = fmaf(xv.z, wv.y, acc2.y);
            acc2.z = fmaf(xv.z, wv.z, acc2.z); acc2.w = fmaf(xv.z, wv.w, acc2.w);
            acc3.x = fmaf(xv.w, wv.x, acc3.x); acc3.y = fmaf(xv.w, wv.y, acc3.y);
            acc3.z = fmaf(xv.w, wv.z, acc3.z); acc3.w = fmaf(xv.w, wv.w, acc3.w);
        }
        float4 p0v = __ldg(&((const float4*)g_p0)[cg]);
        float4 r0 = make_float4(acc0.x+p0v.x, acc0.y+p0v.y, acc0.z+p0v.z, acc0.w+p0v.w);
        float4 r1 = make_float4(acc1.x+p0v.x, acc1.y+p0v.y, acc1.z+p0v.z, acc1.w+p0v.w);
        float4 r2 = make_float4(acc2.x+p0v.x, acc2.y+p0v.y, acc2.z+p0v.z, acc2.w+p0v.w);
        float4 r3 = make_float4(acc3.x+p0v.x, acc3.y+p0v.y, acc3.z+p0v.z, acc3.w+p0v.w);
        float4* Qp4 = (float4*)g_Qp;
        Qp4[(gbase + (ng << 2) + 0) * 32 + cg] = r0;
        Qp4[(gbase + (ng << 2) + 1) * 32 + cg] = r1;
        Qp4[(gbase + (ng << 2) + 2) * 32 + cg] = r2;
        Qp4[(gbase + (ng << 2) + 3) * 32 + cg] = r3;
    }

    {
        const int j = t & 31, ng = t >> 5;
        float a0 = 0.f, a1 = 0.f, a2 = 0.f, a3 = 0.f;
        #pragma unroll 8
        for (int i = 0; i < 128; ++i) {
            float w = __ldg(&g_Pqt[i * 32 + j]);
            float4 xv = *(const float4*)&xs[i][ng << 2];
            a0 = fmaf(w, xv.x, a0);
            a1 = fmaf(w, xv.y, a1);
            a2 = fmaf(w, xv.z, a2);
            a3 = fmaf(w, xv.w, a3);
        }
        float q0 = __ldg(&g_pq0[j]);
        g_Qpp[(gbase + (ng << 2) + 0) * 32 + j] = a0 + q0;
        g_Qpp[(gbase + (ng << 2) + 1) * 32 + j] = a1 + q0;
        g_Qpp[(gbase + (ng << 2) + 2) * 32 + j] = a2 + q0;
        g_Qpp[(gbase + (ng << 2) + 3) * 32 + j] = a3 + q0;
    }
}

// ---------------- shared memory layout for main ----------------
struct __align__(16) SM {
    __half E[64][136];     // fp16 sin/cos embedding (row stride 272B, ldmatrix-friendly)
    float nbf[64 * 128];   // gathered neighbor features
    float part[2 * 2176];  // MLP fp32 partials [2 khalf][64 r][34 stride]
    float rh[64 * 33];     // relu hidden
    float Qp[4][128];
    float Qpp[4][32];
    float dp[64][4];
    float Bg[256];
    float logit[64];
    float attn[64];
    float rden[4];
    float ctr[4][4];
    int   idx[64];
};

// ---------------- main kernel: 4 points/block ----------------
__global__ __launch_bounds__(THREADS) void lsga_main_kernel(
    const float* __restrict__ coords, const void* __restrict__ idxp,
    const float* __restrict__ Bg, const float* __restrict__ b1) {

    extern __shared__ char smem_raw[];
    SM* sm = reinterpret_cast<SM*>(smem_raw);

    const int t = threadIdx.x;
    const int g0 = blockIdx.x * PTS;
    const int b = g0 >> 13;
    const int n0 = g0 & (NN - 1);
    const size_t base = (size_t)b * NN + n0;

    // ---- P0: loads ----
    #pragma unroll
    for (int m = 0; m < 2; ++m) {
        int e = (m << 8) + t;
        int p = e >> 7, c = e & 127;
        sm->Qp[p][c] = g_Qp[(base + p) * 128 + c];
    }
    if (t < 128) {
        int p = t >> 5, j = t & 31;
        sm->Qpp[p][j] = g_Qpp[(base + p) * 32 + j];
    }
    sm->Bg[t] = Bg[t] * TWO_PI;
    if (t < 64) {
        long long v;
        if (g_idx64) v = ((const long long*)idxp)[base * 16 + t];
        else         v = (long long)((const int*)idxp)[base * 16 + t];
        sm->idx[t] = (int)v;
    }
    if (t < 16) {
        int p = t >> 2, a = t & 3;
        sm->ctr[p][a] = coords[(base + p) * 4 + a];
    }
    __syncthreads();

    // ---- P1: delta-p + neighbor gather ----
    {
        int r = t >> 2, a = t & 3, p = t >> 6;
        sm->dp[r][a] = coords[((size_t)b * NN + sm->idx[r]) * 4 + a] - sm->ctr[p][a];
    }
    #pragma unroll
    for (int m = 0; m < 8; ++m) {
        int i = (m << 8) + t;
        int r = i >> 5, q = i & 31;
        const float4* src = (const float4*)&g_xsT[((size_t)b * NN + sm->idx[r]) * 128];
        ((float4*)sm->nbf)[r * 32 + q] = __ldg(src + q);
    }
    __syncthreads();

    // ---- P2: Fourier sincos -> fp16 E ----
    #pragma unroll
    for (int m = 0; m < 8; ++m) {
        int item = (m << 8) + t;            // 0..2047, 2 d-values each
        int r = item >> 5, d = (item & 31) << 1;
        float pr0 = sm->dp[r][0] * sm->Bg[d]
                  + sm->dp[r][1] * sm->Bg[64 + d]
                  + sm->dp[r][2] * sm->Bg[128 + d]
                  + sm->dp[r][3] * sm->Bg[192 + d];
        float pr1 = sm->dp[r][0] * sm->Bg[d + 1]
                  + sm->dp[r][1] * sm->Bg[64 + d + 1]
                  + sm->dp[r][2] * sm->Bg[128 + d + 1]
                  + sm->dp[r][3] * sm->Bg[192 + d + 1];
        float s0, c0, s1, c1;
        __sincosf(pr0, &s0, &c0);
        __sincosf(pr1, &s1, &c1);
        *(half2*)&sm->E[r][d]      = __floats2half2_rn(s0, s1);
        *(half2*)&sm->E[r][64 + d] = __floats2half2_rn(c0, c1);
    }
    __syncthreads();

    // ---- P3: hidden MLP GEMM via tensor cores (64r x 32j x 128d) ----
    {
        const int w = t >> 5, lane = t & 31;
        const int mtile = w & 3;           // rows r0 = mtile*16
        const int khalf = w >> 2;          // k in [khalf*64, khalf*64+64)
        const int r0 = mtile << 4;

        uint32_t A[4][4];
        #pragma unroll
        for (int ks = 0; ks < 4; ++ks) {
            int k0 = (khalf << 6) + (ks << 4);
            const __half* ea = &sm->E[r0 + (lane & 15)][k0 + ((lane >> 4) << 3)];
            ldmatrix_x4(A[ks], (uint32_t)__cvta_generic_to_shared(ea));
        }

        float c[4][4];
        #pragma unroll
        for (int nt = 0; nt < 4; ++nt)
            #pragma unroll
            for (int q = 0; q < 4; ++q) c[nt][q] = 0.f;

        const int bj = (lane >> 2);        // n within tile
        const int bk = (lane & 3) << 1;    // k pair base
        #pragma unroll
        for (int nt = 0; nt < 4; ++nt) {
            #pragma unroll
            for (int ks = 0; ks < 4; ++ks) {
                int k0 = (khalf << 6) + (ks << 4);
                const __half* wr = &g_W1h[((nt << 3) + bj) * 128 + k0 + bk];
                uint32_t b0 = *(const uint32_t*)wr;
                uint32_t b1v = *(const uint32_t*)(wr + 8);
                mma16816(c[nt], A[ks], b0, b1v);
            }
        }

        float* pp = &sm->part[khalf * 2176];
        const int rr = r0 + (lane >> 2);
        const int colb = (lane & 3) << 1;
        #pragma unroll
        for (int nt = 0; nt < 4; ++nt) {
            int col = (nt << 3) + colb;
            *(float2*)&pp[rr * 34 + col]       = make_float2(c[nt][0], c[nt][1]);
            *(float2*)&pp[(rr + 8) * 34 + col] = make_float2(c[nt][2], c[nt][3]);
        }
    }
    __syncthreads();

    // ---- P4: relu hidden combine ----
    #pragma unroll
    for (int m = 0; m < 8; ++m) {
        int i = (m << 8) + t;
        int r = i >> 5, j = i & 31;
        float h = __ldg(&b1[j]) + sm->part[r * 34 + j] + sm->part[2176 + r * 34 + j];
        sm->rh[r * 33 + j] = fmaxf(h, 0.f);
    }
    __syncthreads();

    // ---- P5: logits ----
    {
        const int l = t & 31, w = t >> 5;
        #pragma unroll
        for (int rr = 0; rr < 8; ++rr) {
            int r = (w << 3) + rr;
            int p = r >> 4;
            float val = sm->Qp[p][l]      * sm->nbf[r * 128 + l]
                      + sm->Qp[p][l + 32] * sm->nbf[r * 128 + l + 32]
                      + sm->Qp[p][l + 64] * sm->nbf[r * 128 + l + 64]
                      + sm->Qp[p][l + 96] * sm->nbf[r * 128 + l + 96]
                      + sm->rh[r * 33 + l] * sm->Qpp[p][l];
            #pragma unroll
            for (int off = 16; off; off >>= 1)
                val += __shfl_xor_sync(0xffffffffu, val, off);
            if (l == 0) sm->logit[r] = val * RSQRT_C;
        }
    }
    __syncthreads();

    // ---- P6: softmax ----
    if (t < 64) {
        int p = t >> 4, k = t & 15;
        float lg = sm->logit[t];
        float mx = lg;
        #pragma unroll
        for (int off = 8; off; off >>= 1)
            mx = fmaxf(mx, __shfl_xor_sync(0xffffffffu, mx, off));
        float e = __expf(lg - mx);
        float s = e;
        #pragma unroll
        for (int off = 8; off; off >>= 1)
            s += __shfl_xor_sync(0xffffffffu, s, off);
        sm->attn[t] = e;
        if (k == 0) sm->rden[p] = 1.0f / s;
    }
    __syncthreads();

    // ---- P7: attention-weighted aggregates -> g_v ----
    #pragma unroll
    for (int m = 0; m < 2; ++m) {
        int i = (m << 8) + t;
        int p = i >> 7, c = i & 127;
        float fa = 0.f;
        #pragma unroll
        for (int k = 0; k < 16; ++k)
            fa = fmaf(sm->attn[p * 16 + k], sm->nbf[(p * 16 + k) * 128 + c], fa);
        g_v[(base + p) * 160 + c] = fa * sm->rden[p];
    }
    if (t < 128) {
        int p = t >> 5, j = t & 31;
        float ha = 0.f;
        #pragma unroll
        for (int k = 0; k < 16; ++k)
            ha = fmaf(sm->attn[p * 16 + k], sm->rh[(p * 16 + k) * 33 + j], ha);
        g_v[(base + p) * 160 + 128 + j] = ha * sm->rden[p];
    }
}

// ---------------- output GEMM + transpose: 32 points/block ----------------
__global__ __launch_bounds__(256) void out_kernel(float* __restrict__ out) {
    __shared__ float vs[160][36];
    __shared__ float os[128][33];
    const int t = threadIdx.x;
    const int blk = blockIdx.x;
    const int b = blk >> 8;
    const int n0 = (blk & 255) << 5;
    const size_t gbase = (size_t)b * NN + n0;

    #pragma unroll
    for (int m = 0; m < 20; ++m) {
        int e = (m << 8) + t;
        int n = e / 160;
        int i = e - n * 160;
        vs[i][n] = g_v[(gbase + n) * 160 + i];
    }
    __syncthreads();

    {
        const int cg = t & 31, ng = t >> 5;
        float4 acc0 = make_float4(0,0,0,0), acc1 = acc0, acc2 = acc0, acc3 = acc0;
        const float4* Wc4 = (const float4*)g_Wcat;
        #pragma unroll 8
        for (int i = 0; i < 160; ++i) {
            float4 wv = __ldg(&Wc4[i * 32 + cg]);
            float4 xv = *(const float4*)&vs[i][ng << 2];
            acc0.x = fmaf(xv.x, wv.x, acc0.x); acc0.y = fmaf(xv.x, wv.y, acc0.y);
            acc0.z = fmaf(xv.x, wv.z, acc0.z); acc0.w = fmaf(xv.x, wv.w, acc0.w);
            acc1.x = fmaf(xv.y, wv.x, acc1.x); acc1.y = fmaf(xv.y, wv.y, acc1.y);
            acc1.z = fmaf(xv.y, wv.z, acc1.z); acc1.w = fmaf(xv.y, wv.w, acc1.w);
            acc2.x = fmaf(xv.z, wv.x, acc2.x); acc2.y = fmaf(xv.z, wv.y, acc2.y);
            acc2.z = fmaf(xv.z, wv.z, acc2.z); acc2.w = fmaf(xv.z, wv.w, acc2.w);
            acc3.x = fmaf(xv.w, wv.x, acc3.x); acc3.y = fmaf(xv.w, wv.y, acc3.y);
            acc3.z = fmaf(xv.w, wv.z, acc3.z); acc3.w = fmaf(xv.w, wv.w, acc3.w);
        }
        float4 b3v = __ldg(&((const float4*)g_b3)[cg]);
        int nb = ng << 2, cb = cg << 2;
        os[cb + 0][nb + 0] = acc0.x + b3v.x; os[cb + 1][nb + 0] = acc0.y + b3v.y;
        os[cb + 2][nb + 0] = acc0.z + b3v.z; os[cb + 3][nb + 0] = acc0.w + b3v.w;
        os[cb + 0][nb + 1] = acc1.x + b3v.x; os[cb + 1][nb + 1] = acc1.y + b3v.y;
        os[cb + 2][nb + 1] = acc1.z + b3v.z; os[cb + 3][nb + 1] = acc1.w + b3v.w;
        os[cb + 0][nb + 2] = acc2.x + b3v.x; os[cb + 1][nb + 2] = acc2.y + b3v.y;
        os[cb + 2][nb + 2] = acc2.z + b3v.z; os[cb + 3][nb + 2] = acc2.w + b3v.w;
        os[cb + 0][nb + 3] = acc3.x + b3v.x; os[cb + 1][nb + 3] = acc3.y + b3v.y;
        os[cb + 2][nb + 3] = acc3.z + b3v.z; os[cb + 3][nb + 3] = acc3.w + b3v.w;
    }
    __syncthreads();

    #pragma unroll
    for (int m = 0; m < 16; ++m) {
        int e = (m << 8) + t;
        int c = e >> 5, nn = e & 31;
        out[((size_t)(b * 128 + c) << 13) + n0 + nn] = os[c][nn];
    }
}

// ---------------- launch ----------------
extern "C" void kernel_launch(void* const* d_in, const int* in_sizes, int n_in,
                              void* d_out, int out_size) {
    const float* x      = (const float*)d_in[0];
    const float* coords = (const float*)d_in[1];
    const void*  idx    = d_in[2];
    const float* Bg     = (const float*)d_in[3];
    const float* W1     = (const float*)d_in[4];
    const float* b1     = (const float*)d_in[5];
    const float* W2     = (const float*)d_in[6];
    const float* b2     = (const float*)d_in[7];
    const float* Wq     = (const float*)d_in[8];
    const float* bq     = (const float*)d_in[9];
    const float* Wk     = (const float*)d_in[10];
    const float* Wv     = (const float*)d_in[12];
    const float* bv     = (const float*)d_in[13];
    const float* Wo     = (const float*)d_in[14];
    const float* bo     = (const float*)d_in[15];
    float* out = (float*)d_out;

    static bool attr_set = false;
    if (!attr_set) {
        cudaFuncSetAttribute(lsga_main_kernel,
                             cudaFuncAttributeMaxDynamicSharedMemorySize,
                             (int)sizeof(SM));
        attr_set = true;
    }

    prep1_kernel<<<129, 128>>>(Wq, Wk, Wv, Wo, bq, (const int*)idx);
    prep2_kernel<<<128, 128>>>(W2, Wo, b2, bv, bo, W1);
    pre_kernel<<<(BB * NN) / 32, 256>>>(x);
    lsga_main_kernel<<<(BB * NN) / PTS, THREADS, sizeof(SM)>>>(coords, idx, Bg, b1);
    out_kernel<<<(BB * NN) / 32, 256>>>(out);
}

// round 5
// speedup vs baseline: 3.5507x; 1.5409x over previous
#include <cuda_runtime.h>
#include <cuda_fp16.h>
#include <math.h>
#include <stdint.h>

#define BB 2
#define CC 128
#define NN 8192
#define PTS 4
#define THREADS 256
#define TWO_PI 6.283185307179586f
#define RSQRT_C 0.08838834764831845f   // 1/sqrt(128)

// ---------------- device scratch ----------------
__device__ float g_xsT[BB * NN * CC];     // xs transposed to [B][N][C]
__device__ float g_Qp [BB * NN * CC];     // Q' per point [n][c]
__device__ float g_Qpp[BB * NN * 32];     // Q'' per point [n][j]
__device__ float g_v  [BB * NN * 160];    // attention aggregates [n][160]
__device__ float g_Pt[CC * CC];           // Pt[i*128+c] = P[c][i],  P = Wk^T Wq
__device__ float g_p0[CC];                // Wk^T bq
__device__ float g_Pqt[CC * 32];          // Pqt[i*32+j] = Pq[j][i], Pq = W2 P
__device__ float g_pq0[32];               // W2 p0
__device__ float g_Wcat[160 * CC];        // rows 0..127: (WoWv)^T ; rows 128..159: (WoWvW2^T)^T
__device__ float g_b3[CC];                // fused output bias
__device__ __half g_W1h[32 * 128];        // W1 transposed to [j][d], fp16
__device__ int   g_idx64;

// ---------------- mma helpers ----------------
__device__ __forceinline__ void ldmatrix_x4(uint32_t* a, uint32_t saddr) {
    asm volatile("ldmatrix.sync.aligned.m8n8.x4.shared.b16 {%0,%1,%2,%3}, [%4];"
                 : "=r"(a[0]), "=r"(a[1]), "=r"(a[2]), "=r"(a[3]) : "r"(saddr));
}
__device__ __forceinline__ void ldmatrix_x2(uint32_t& b0, uint32_t& b1, uint32_t saddr) {
    asm volatile("ldmatrix.sync.aligned.m8n8.x2.shared.b16 {%0,%1}, [%2];"
                 : "=r"(b0), "=r"(b1) : "r"(saddr));
}
__device__ __forceinline__ void mma16816(float* c, const uint32_t* a, uint32_t b0, uint32_t b1) {
    asm volatile("mma.sync.aligned.m16n8k16.row.col.f32.f16.f16.f32 "
                 "{%0,%1,%2,%3}, {%4,%5,%6,%7}, {%8,%9}, {%0,%1,%2,%3};"
                 : "+f"(c[0]), "+f"(c[1]), "+f"(c[2]), "+f"(c[3])
                 : "r"(a[0]), "r"(a[1]), "r"(a[2]), "r"(a[3]), "r"(b0), "r"(b1));
}

// ---------------- prep stage 1 (+ idx dtype detect in block 128) ----------------
__global__ void prep1_kernel(const float* __restrict__ Wq, const float* __restrict__ Wk,
                             const float* __restrict__ Wv, const float* __restrict__ Wo,
                             const float* __restrict__ bq, const int* __restrict__ idx32) {
    int i = blockIdx.x, t = threadIdx.x;
    if (i == 128) {
        __shared__ int any;
        if (t == 0) any = 0;
        __syncthreads();
        int local = 0;
        for (int e = t; e < 2048; e += 128)
            if (idx32[2 * e + 1] != 0) local = 1;
        if (local) atomicOr(&any, 1);
        __syncthreads();
        if (t == 0) g_idx64 = (any ? 0 : 1);
        return;
    }
    float a = 0.f, w = 0.f;
    for (int o = 0; o < 128; ++o) {
        a += Wk[o * 128 + t] * Wq[o * 128 + i];   // P[t][i]
        w += Wo[t * 128 + o] * Wv[o * 128 + i];   // Wfuse[t][i]
    }
    g_Pt[i * 128 + t] = a;
    g_Wcat[i * 128 + t] = w;
    if (i == 0) {
        float p = 0.f;
        for (int o = 0; o < 128; ++o) p += Wk[o * 128 + t] * bq[o];
        g_p0[t] = p;
    }
}

// ---------------- prep stage 2 (+ W1 fp16 transpose) ----------------
__global__ void prep2_kernel(const float* __restrict__ W2, const float* __restrict__ Wo,
                             const float* __restrict__ b2, const float* __restrict__ bv,
                             const float* __restrict__ bo, const float* __restrict__ W1) {
    int i = blockIdx.x, t = threadIdx.x;
    if (t < 32) {
        float a = 0.f;
        for (int c = 0; c < 128; ++c) a += W2[t * 128 + c] * g_Pt[i * 128 + c];
        g_Pqt[i * 32 + t] = a;
        g_W1h[t * 128 + i] = __float2half(W1[i * 32 + t]);   // Wt[j][d]
    }
    if (i < 32) {
        float a = 0.f;
        for (int ii = 0; ii < 128; ++ii) a += g_Wcat[ii * 128 + t] * W2[i * 128 + ii];
        g_Wcat[(128 + i) * 128 + t] = a;
    }
    if (i == 0) {
        if (t < 32) {
            float a = 0.f;
            for (int c = 0; c < 128; ++c) a += W2[t * 128 + c] * g_p0[c];
            g_pq0[t] = a;
        }
        float a = 0.f;
        for (int ii = 0; ii < 128; ++ii) a += g_Wcat[ii * 128 + t] * b2[ii];
        for (int c = 0; c < 128; ++c)   a += Wo[t * 128 + c] * bv[c];
        g_b3[t] = a + bo[t];
    }
}

// ---------------- pre kernel: transpose + Q' + Q'' GEMMs, 32 points/block ----
__global__ __launch_bounds__(256) void pre_kernel(const float* __restrict__ x) {
    __shared__ float xs[128][36];
    const int t = threadIdx.x;
    const int blk = blockIdx.x;
    const int b = blk >> 8;
    const int n0 = (blk & 255) << 5;
    const size_t gbase = (size_t)b * NN + n0;

    #pragma unroll
    for (int m = 0; m < 16; ++m) {
        int e = (m << 8) + t;
        int i = e >> 5, nn = e & 31;
        xs[i][nn] = x[((size_t)(b * 128 + i) << 13) + n0 + nn];
    }
    __syncthreads();

    #pragma unroll
    for (int m = 0; m < 16; ++m) {
        int e = (m << 8) + t;
        int n = e >> 7, c = e & 127;
        g_xsT[(gbase + n) * 128 + c] = xs[c][n];
    }

    {
        const int cg = t & 31, ng = t >> 5;
        float4 acc0 = make_float4(0,0,0,0), acc1 = acc0, acc2 = acc0, acc3 = acc0;
        const float4* Pt4 = (const float4*)g_Pt;
        #pragma unroll 8
        for (int i = 0; i < 128; ++i) {
            float4 wv = __ldg(&Pt4[i * 32 + cg]);
            float4 xv = *(const float4*)&xs[i][ng << 2];
            acc0.x = fmaf(xv.x, wv.x, acc0.x); acc0.y = fmaf(xv.x, wv.y, acc0.y);
            acc0.z = fmaf(xv.x, wv.z, acc0.z); acc0.w = fmaf(xv.x, wv.w, acc0.w);
            acc1.x = fmaf(xv.y, wv.x, acc1.x); acc1.y = fmaf(xv.y, wv.y, acc1.y);
            acc1.z = fmaf(xv.y, wv.z, acc1.z); acc1.w = fmaf(xv.y, wv.w, acc1.w);
            acc2.x = fmaf(xv.z, wv.x, acc2.x); acc2.y = fmaf(xv.z, wv.y, acc2.y);
            acc2.z = fmaf(xv.z, wv.z, acc2.z); acc2.w = fmaf(xv.z, wv.w, acc2.w);
            acc3.x = fmaf(xv.w, wv.x, acc3.x); acc3.y = fmaf(xv.w, wv.y, acc3.y);
            acc3.z = fmaf(xv.w, wv.z, acc3.z); acc3.w = fmaf(xv.w, wv.w, acc3.w);
        }
        float4 p0v = __ldg(&((const float4*)g_p0)[cg]);
        float4 r0 = make_float4(acc0.x+p0v.x, acc0.y+p0v.y, acc0.z+p0v.z, acc0.w+p0v.w);
        float4 r1 = make_float4(acc1.x+p0v.x, acc1.y+p0v.y, acc1.z+p0v.z, acc1.w+p0v.w);
        float4 r2 = make_float4(acc2.x+p0v.x, acc2.y+p0v.y, acc2.z+p0v.z, acc2.w+p0v.w);
        float4 r3 = make_float4(acc3.x+p0v.x, acc3.y+p0v.y, acc3.z+p0v.z, acc3.w+p0v.w);
        float4* Qp4 = (float4*)g_Qp;
        Qp4[(gbase + (ng << 2) + 0) * 32 + cg] = r0;
        Qp4[(gbase + (ng << 2) + 1) * 32 + cg] = r1;
        Qp4[(gbase + (ng << 2) + 2) * 32 + cg] = r2;
        Qp4[(gbase + (ng << 2) + 3) * 32 + cg] = r3;
    }

    {
        const int j = t & 31, ng = t >> 5;
        float a0 = 0.f, a1 = 0.f, a2 = 0.f, a3 = 0.f;
        #pragma unroll 8
        for (int i = 0; i < 128; ++i) {
            float w = __ldg(&g_Pqt[i * 32 + j]);
            float4 xv = *(const float4*)&xs[i][ng << 2];
            a0 = fmaf(w, xv.x, a0);
            a1 = fmaf(w, xv.y, a1);
            a2 = fmaf(w, xv.z, a2);
            a3 = fmaf(w, xv.w, a3);
        }
        float q0 = __ldg(&g_pq0[j]);
        g_Qpp[(gbase + (ng << 2) + 0) * 32 + j] = a0 + q0;
        g_Qpp[(gbase + (ng << 2) + 1) * 32 + j] = a1 + q0;
        g_Qpp[(gbase + (ng << 2) + 2) * 32 + j] = a2 + q0;
        g_Qpp[(gbase + (ng << 2) + 3) * 32 + j] = a3 + q0;
    }
}

// ---------------- shared memory layout for main (~44KB) ----------------
struct __align__(16) SM {
    __half E[64][136];     // fp16 sin/cos embedding, 272B row stride
    __half W1s[32][136];   // fp16 W1^T [j][d], 272B row stride
    float rh[64][34];      // relu hidden
    float Qp[4][128];
    float Qpp[4][32];
    float dp[64][4];
    float Bg[256];
    float vpart[8][128];   // per-warp feature aggregates
    float logit[64];
    float attn[64];
    float rden[4];
    float ctr[4][4];
    int   idx[64];
};

// ---------------- main kernel: 4 points/block, nbf in registers ----------------
__global__ __launch_bounds__(THREADS, 4) void lsga_main_kernel(
    const float* __restrict__ coords, const void* __restrict__ idxp,
    const float* __restrict__ Bg, const float* __restrict__ b1) {

    extern __shared__ char smem_raw[];
    SM* sm = reinterpret_cast<SM*>(smem_raw);

    const int t = threadIdx.x;
    const int lane = t & 31;
    const int w = t >> 5;
    const int g0 = blockIdx.x * PTS;
    const int b = g0 >> 13;
    const int n0 = g0 & (NN - 1);
    const size_t base = (size_t)b * NN + n0;

    // ---- P0: loads ----
    #pragma unroll
    for (int m = 0; m < 2; ++m) {
        int e = (m << 8) + t;
        int p = e >> 7, c = e & 127;
        sm->Qp[p][c] = g_Qp[(base + p) * 128 + c];
    }
    if (t < 128) {
        int p = t >> 5, j = t & 31;
        sm->Qpp[p][j] = g_Qpp[(base + p) * 32 + j];
    }
    sm->Bg[t] = Bg[t] * TWO_PI;
    #pragma unroll
    for (int m = 0; m < 2; ++m) {
        int e = (m << 8) + t;                 // 0..511 chunks of 8 halves
        int j = e >> 4, c0 = (e & 15) << 3;
        *(uint4*)&sm->W1s[j][c0] = *(const uint4*)&g_W1h[j * 128 + c0];
    }
    if (t < 64) {
        long long v;
        if (g_idx64) v = ((const long long*)idxp)[base * 16 + t];
        else         v = (long long)((const int*)idxp)[base * 16 + t];
        sm->idx[t] = (int)v;
    }
    if (t < 16) {
        int p = t >> 2, a = t & 3;
        sm->ctr[p][a] = coords[(base + p) * 4 + a];
    }
    __syncthreads();

    // ---- P1: delta-p + neighbor gather into registers ----
    {
        int r = t >> 2, a = t & 3, p = t >> 6;
        sm->dp[r][a] = coords[((size_t)b * NN + sm->idx[r]) * 4 + a] - sm->ctr[p][a];
    }
    float4 nbf[8];                         // rows 8w..8w+7, channels 4*lane..+3
    #pragma unroll
    for (int rr = 0; rr < 8; ++rr) {
        int r = (w << 3) + rr;
        nbf[rr] = __ldg((const float4*)&g_xsT[((size_t)b * NN + sm->idx[r]) * 128 + (lane << 2)]);
    }
    __syncthreads();

    // ---- P2: Fourier sincos -> fp16 E ----
    #pragma unroll
    for (int m = 0; m < 8; ++m) {
        int item = (m << 8) + t;            // 0..2047, 2 d-values each
        int r = item >> 5, d = (item & 31) << 1;
        float pr0 = sm->dp[r][0] * sm->Bg[d]
                  + sm->dp[r][1] * sm->Bg[64 + d]
                  + sm->dp[r][2] * sm->Bg[128 + d]
                  + sm->dp[r][3] * sm->Bg[192 + d];
        float pr1 = sm->dp[r][0] * sm->Bg[d + 1]
                  + sm->dp[r][1] * sm->Bg[64 + d + 1]
                  + sm->dp[r][2] * sm->Bg[128 + d + 1]
                  + sm->dp[r][3] * sm->Bg[192 + d + 1];
        float s0, c0, s1, c1;
        __sincosf(pr0, &s0, &c0);
        __sincosf(pr1, &s1, &c1);
        *(half2*)&sm->E[r][d]      = __floats2half2_rn(s0, s1);
        *(half2*)&sm->E[r][64 + d] = __floats2half2_rn(c0, c1);
    }
    __syncthreads();

    // ---- P3: hidden MLP via tensor cores, m16 x n16 x k128 per warp ----
    {
        const int mtile = w & 3;           // rows r0 = mtile*16
        const int nh = w >> 2;             // j range [nh*16, nh*16+16)
        const int r0 = mtile << 4;
        const int jn0 = nh << 4;

        float c[2][4];
        #pragma unroll
        for (int nt = 0; nt < 2; ++nt)
            #pragma unroll
            for (int q = 0; q < 4; ++q) c[nt][q] = 0.f;

        #pragma unroll
        for (int ks = 0; ks < 8; ++ks) {
            int k0 = ks << 4;
            uint32_t A[4];
            const __half* ea = &sm->E[r0 + (lane & 15)][k0 + ((lane >> 4) << 3)];
            ldmatrix_x4(A, (uint32_t)__cvta_generic_to_shared(ea));
            #pragma unroll
            for (int nt = 0; nt < 2; ++nt) {
                uint32_t b0, b1v;
                const __half* wb = &sm->W1s[jn0 + (nt << 3) + (lane & 7)]
                                          [k0 + (((lane >> 3) & 1) << 3)];
                ldmatrix_x2(b0, b1v, (uint32_t)__cvta_generic_to_shared(wb));
                mma16816(c[nt], A, b0, b1v);
            }
        }

        const int row1 = r0 + (lane >> 2);
        #pragma unroll
        for (int nt = 0; nt < 2; ++nt) {
            int col = jn0 + (nt << 3) + ((lane & 3) << 1);
            float bb0 = __ldg(&b1[col]), bb1 = __ldg(&b1[col + 1]);
            *(float2*)&sm->rh[row1][col] =
                make_float2(fmaxf(c[nt][0] + bb0, 0.f), fmaxf(c[nt][1] + bb1, 0.f));
            *(float2*)&sm->rh[row1 + 8][col] =
                make_float2(fmaxf(c[nt][2] + bb0, 0.f), fmaxf(c[nt][3] + bb1, 0.f));
        }
    }
    __syncthreads();

    // ---- P5: logits from register nbf ----
    {
        const int p = w >> 1;
        float4 qp4 = *(const float4*)&sm->Qp[p][lane << 2];
        float qpp = sm->Qpp[p][lane];
        #pragma unroll
        for (int rr = 0; rr < 8; ++rr) {
            int r = (w << 3) + rr;
            float val = qp4.x * nbf[rr].x + qp4.y * nbf[rr].y
                      + qp4.z * nbf[rr].z + qp4.w * nbf[rr].w
                      + sm->rh[r][lane] * qpp;
            #pragma unroll
            for (int off = 16; off; off >>= 1)
                val += __shfl_xor_sync(0xffffffffu, val, off);
            if (lane == 0) sm->logit[r] = val * RSQRT_C;
        }
    }
    __syncthreads();

    // ---- P6: softmax ----
    if (t < 64) {
        int p = t >> 4, k = t & 15;
        float lg = sm->logit[t];
        float mx = lg;
        #pragma unroll
        for (int off = 8; off; off >>= 1)
            mx = fmaxf(mx, __shfl_xor_sync(0xffffffffu, mx, off));
        float e = __expf(lg - mx);
        float s = e;
        #pragma unroll
        for (int off = 8; off; off >>= 1)
            s += __shfl_xor_sync(0xffffffffu, s, off);
        sm->attn[t] = e;
        if (k == 0) sm->rden[p] = 1.0f / s;
    }
    __syncthreads();

    // ---- P7: aggregates ----
    {
        float4 fa = make_float4(0.f, 0.f, 0.f, 0.f);
        #pragma unroll
        for (int rr = 0; rr < 8; ++rr) {
            float a = sm->attn[(w << 3) + rr];
            fa.x = fmaf(a, nbf[rr].x, fa.x);
            fa.y = fmaf(a, nbf[rr].y, fa.y);
            fa.z = fmaf(a, nbf[rr].z, fa.z);
            fa.w = fmaf(a, nbf[rr].w, fa.w);
        }
        *(float4*)&sm->vpart[w][lane << 2] = fa;
    }
    if (t < 128) {
        int p = t >> 5, j = t & 31;
        float ha = 0.f;
        #pragma unroll
        for (int k = 0; k < 16; ++k)
            ha = fmaf(sm->attn[p * 16 + k], sm->rh[p * 16 + k][j], ha);
        g_v[(base + p) * 160 + 128 + j] = ha * sm->rden[p];
    }
    __syncthreads();

    #pragma unroll
    for (int m = 0; m < 2; ++m) {
        int e = (m << 8) + t;              // 0..511
        int p = e >> 7, c = e & 127;
        g_v[(base + p) * 160 + c] =
            (sm->vpart[2 * p][c] + sm->vpart[2 * p + 1][c]) * sm->rden[p];
    }
}

// ---------------- output GEMM + transpose: 32 points/block ----------------
__global__ __launch_bounds__(256) void out_kernel(float* __restrict__ out) {
    __shared__ float vs[160][36];
    __shared__ float os[128][33];
    const int t = threadIdx.x;
    const int blk = blockIdx.x;
    const int b = blk >> 8;
    const int n0 = (blk & 255) << 5;
    const size_t gbase = (size_t)b * NN + n0;

    #pragma unroll
    for (int m = 0; m < 20; ++m) {
        int e = (m << 8) + t;
        int n = e / 160;
        int i = e - n * 160;
        vs[i][n] = g_v[(gbase + n) * 160 + i];
    }
    __syncthreads();

    {
        const int cg = t & 31, ng = t >> 5;
        float4 acc0 = make_float4(0,0,0,0), acc1 = acc0, acc2 = acc0, acc3 = acc0;
        const float4* Wc4 = (const float4*)g_Wcat;
        #pragma unroll 8
        for (int i = 0; i < 160; ++i) {
            float4 wv = __ldg(&Wc4[i * 32 + cg]);
            float4 xv = *(const float4*)&vs[i][ng << 2];
            acc0.x = fmaf(xv.x, wv.x, acc0.x); acc0.y = fmaf(xv.x, wv.y, acc0.y);
            acc0.z = fmaf(xv.x, wv.z, acc0.z); acc0.w = fmaf(xv.x, wv.w, acc0.w);
            acc1.x = fmaf(xv.y, wv.x, acc1.x); acc1.y = fmaf(xv.y, wv.y, acc1.y);
            acc1.z = fmaf(xv.y, wv.z, acc1.z); acc1.w = fmaf(xv.y, wv.w, acc1.w);
            acc2.x = fmaf(xv.z, wv.x, acc2.x); acc2.y = fmaf(xv.z, wv.y, acc2.y);
            acc2.z = fmaf(xv.z, wv.z, acc2.z); acc2.w = fmaf(xv.z, wv.w, acc2.w);
            acc3.x = fmaf(xv.w, wv.x, acc3.x); acc3.y = fmaf(xv.w, wv.y, acc3.y);
            acc3.z = fmaf(xv.w, wv.z, acc3.z); acc3.w = fmaf(xv.w, wv.w, acc3.w);
        }
        float4 b3v = __ldg(&((const float4*)g_b3)[cg]);
        int nb = ng << 2, cb = cg << 2;
        os[cb + 0][nb + 0] = acc0.x + b3v.x; os[cb + 1][nb + 0] = acc0.y + b3v.y;
        os[cb + 2][nb + 0] = acc0.z + b3v.z; os[cb + 3][nb + 0] = acc0.w + b3v.w;
        os[cb + 0][nb + 1] = acc1.x + b3v.x; os[cb + 1][nb + 1] = acc1.y + b3v.y;
        os[cb + 2][nb + 1] = acc1.z + b3v.z; os[cb + 3][nb + 1] = acc1.w + b3v.w;
        os[cb + 0][nb + 2] = acc2.x + b3v.x; os[cb + 1][nb + 2] = acc2.y + b3v.y;
        os[cb + 2][nb + 2] = acc2.z + b3v.z; os[cb + 3][nb + 2] = acc2.w + b3v.w;
        os[cb + 0][nb + 3] = acc3.x + b3v.x; os[cb + 1][nb + 3] = acc3.y + b3v.y;
        os[cb + 2][nb + 3] = acc3.z + b3v.z; os[cb + 3][nb + 3] = acc3.w + b3v.w;
    }
    __syncthreads();

    #pragma unroll
    for (int m = 0; m < 16; ++m) {
        int e = (m << 8) + t;
        int c = e >> 5, nn = e & 31;
        out[((size_t)(b * 128 + c) << 13) + n0 + nn] = os[c][nn];
    }
}

// ---------------- launch ----------------
extern "C" void kernel_launch(void* const* d_in, const int* in_sizes, int n_in,
                              void* d_out, int out_size) {
    const float* x      = (const float*)d_in[0];
    const float* coords = (const float*)d_in[1];
    const void*  idx    = d_in[2];
    const float* Bg     = (const float*)d_in[3];
    const float* W1     = (const float*)d_in[4];
    const float* b1     = (const float*)d_in[5];
    const float* W2     = (const float*)d_in[6];
    const float* b2     = (const float*)d_in[7];
    const float* Wq     = (const float*)d_in[8];
    const float* bq     = (const float*)d_in[9];
    const float* Wk     = (const float*)d_in[10];
    const float* Wv     = (const float*)d_in[12];
    const float* bv     = (const float*)d_in[13];
    const float* Wo     = (const float*)d_in[14];
    const float* bo     = (const float*)d_in[15];
    float* out = (float*)d_out;

    static bool attr_set = false;
    if (!attr_set) {
        cudaFuncSetAttribute(lsga_main_kernel,
                             cudaFuncAttributeMaxDynamicSharedMemorySize,
                             (int)sizeof(SM));
        attr_set = true;
    }

    prep1_kernel<<<129, 128>>>(Wq, Wk, Wv, Wo, bq, (const int*)idx);
    prep2_kernel<<<128, 128>>>(W2, Wo, b2, bv, bo, W1);
    pre_kernel<<<(BB * NN) / 32, 256>>>(x);
    lsga_main_kernel<<<(BB * NN) / PTS, THREADS, sizeof(SM)>>>(coords, idx, Bg, b1);
    out_kernel<<<(BB * NN) / 32, 256>>>(out);
}

// round 6
// speedup vs baseline: 4.6473x; 1.3088x over previous
#include <cuda_runtime.h>
#include <cuda_fp16.h>
#include <math.h>
#include <stdint.h>

#define BB 2
#define CC 128
#define NN 8192
#define PTS 4
#define THREADS 256
#define TWO_PI 6.283185307179586f
#define RSQRT_C 0.08838834764831845f   // 1/sqrt(128)

// ---------------- device scratch ----------------
__device__ __half g_xsTh[BB * NN * CC];    // xs transposed to [B][N][C], fp16
__device__ float  g_Qp [BB * NN * CC];     // Q' per point [n][c]
__device__ float  g_Qpp[BB * NN * 32];     // Q'' per point [n][j]
__device__ __half g_vh [BB * NN * 160];    // attention aggregates [n][160], fp16
__device__ float  g_Pt[CC * CC];           // Pt[i*128+c] = P[c][i],  P = Wk^T Wq
__device__ float  g_p0[CC];                // Wk^T bq
__device__ float  g_Pqt[CC * 32];          // Pqt[i*32+j] = Pq[j][i]
__device__ float  g_pq0[32];               // W2 p0
__device__ float  g_Wcat[160 * CC];        // (WoWv)^T rows + (WoWvW2^T)^T rows (fp32 staging)
__device__ float  g_b3[CC];                // fused output bias
__device__ __half g_W1h[32 * 128];         // W1^T [j][d], fp16
__device__ __half g_Bh[160 * 128];         // pre GEMM B: rows 0..127 P[c][i], 128..159 Pq[j][i]
__device__ __half g_Wcath[128 * 160];      // out GEMM B: Wfused[o][i], i in 0..159
__device__ int    g_idx64;

// ---------------- mma helpers ----------------
__device__ __forceinline__ void ldmatrix_x4(uint32_t* a, uint32_t saddr) {
    asm volatile("ldmatrix.sync.aligned.m8n8.x4.shared.b16 {%0,%1,%2,%3}, [%4];"
                 : "=r"(a[0]), "=r"(a[1]), "=r"(a[2]), "=r"(a[3]) : "r"(saddr));
}
__device__ __forceinline__ void ldmatrix_x2(uint32_t& b0, uint32_t& b1, uint32_t saddr) {
    asm volatile("ldmatrix.sync.aligned.m8n8.x2.shared.b16 {%0,%1}, [%2];"
                 : "=r"(b0), "=r"(b1) : "r"(saddr));
}
__device__ __forceinline__ void mma16816(float* c, const uint32_t* a, uint32_t b0, uint32_t b1) {
    asm volatile("mma.sync.aligned.m16n8k16.row.col.f32.f16.f16.f32 "
                 "{%0,%1,%2,%3}, {%4,%5,%6,%7}, {%8,%9}, {%0,%1,%2,%3};"
                 : "+f"(c[0]), "+f"(c[1]), "+f"(c[2]), "+f"(c[3])
                 : "r"(a[0]), "r"(a[1]), "r"(a[2]), "r"(a[3]), "r"(b0), "r"(b1));
}

// ---------------- prep stage 1 (+ idx dtype detect) ----------------
__global__ void prep1_kernel(const float* __restrict__ Wq, const float* __restrict__ Wk,
                             const float* __restrict__ Wv, const float* __restrict__ Wo,
                             const float* __restrict__ bq, const int* __restrict__ idx32) {
    int i = blockIdx.x, t = threadIdx.x;
    if (i == 128) {
        __shared__ int any;
        if (t == 0) any = 0;
        __syncthreads();
        int local = 0;
        for (int e = t; e < 2048; e += 128)
            if (idx32[2 * e + 1] != 0) local = 1;
        if (local) atomicOr(&any, 1);
        __syncthreads();
        if (t == 0) g_idx64 = (any ? 0 : 1);
        return;
    }
    float a = 0.f, w = 0.f;
    for (int o = 0; o < 128; ++o) {
        a += Wk[o * 128 + t] * Wq[o * 128 + i];   // P[t][i]
        w += Wo[t * 128 + o] * Wv[o * 128 + i];   // Wfuse[t][i]
    }
    g_Pt[i * 128 + t] = a;
    g_Wcat[i * 128 + t] = w;
    if (i == 0) {
        float p = 0.f;
        for (int o = 0; o < 128; ++o) p += Wk[o * 128 + t] * bq[o];
        g_p0[t] = p;
    }
}

// ---------------- prep stage 2 (+ fp16 packs) ----------------
__global__ void prep2_kernel(const float* __restrict__ W2, const float* __restrict__ Wo,
                             const float* __restrict__ b2, const float* __restrict__ bv,
                             const float* __restrict__ bo, const float* __restrict__ W1) {
    int i = blockIdx.x, t = threadIdx.x;       // i,t in 0..127
    // fp16 B for pre GEMM, rows 0..127 : P[c=t][i]
    g_Bh[t * 128 + i] = __float2half(g_Pt[i * 128 + t]);
    // fp16 B for out GEMM, k<128 part : Wfuse[o=t][i]
    g_Wcath[t * 160 + i] = __float2half(g_Wcat[i * 128 + t]);
    if (t < 32) {
        float a = 0.f;
        for (int c = 0; c < 128; ++c) a += W2[t * 128 + c] * g_Pt[i * 128 + c];
        g_Pqt[i * 32 + t] = a;
        g_Bh[(128 + t) * 128 + i] = __float2half(a);     // Pq[j=t][i]
        g_W1h[t * 128 + i] = __float2half(W1[i * 32 + t]);
    }
    if (i < 32) {
        float a = 0.f;
        for (int ii = 0; ii < 128; ++ii) a += g_Wcat[ii * 128 + t] * W2[i * 128 + ii];
        g_Wcath[t * 160 + 128 + i] = __float2half(a);    // W3[o=t][j=i]
    }
    if (i == 0) {
        if (t < 32) {
            float a = 0.f;
            for (int c = 0; c < 128; ++c) a += W2[t * 128 + c] * g_p0[c];
            g_pq0[t] = a;
        }
        float a = 0.f;
        for (int ii = 0; ii < 128; ++ii) a += g_Wcat[ii * 128 + t] * b2[ii];
        for (int c = 0; c < 128; ++c)   a += Wo[t * 128 + c] * bv[c];
        g_b3[t] = a + bo[t];
    }
}

// ---------------- pre kernel: transpose->fp16 + fused Q'/Q'' tensor GEMM ----
// 32 points/block, m32 x n160 x k128
struct __align__(16) SMPRE {
    __half As[32][136];    // x^T tile [pt][c], 272B row stride
    __half Bs[160][136];   // [P;Pq] [chan][i]
};
__global__ __launch_bounds__(256) void pre_kernel(const float* __restrict__ x) {
    extern __shared__ char smem_raw[];
    SMPRE* sm = reinterpret_cast<SMPRE*>(smem_raw);
    const int t = threadIdx.x;
    const int lane = t & 31, w = t >> 5;
    const int blk = blockIdx.x;
    const int b = blk >> 8;
    const int n0 = (blk & 255) << 5;
    const size_t gbase = (size_t)b * NN + n0;

    // load x tile [128c][32n] -> As[n][c] fp16
    #pragma unroll
    for (int m = 0; m < 16; ++m) {
        int e = (m << 8) + t;
        int c = e >> 5, nn = e & 31;
        sm->As[nn][c] = __float2half(x[((size_t)(b * 128 + c) << 13) + n0 + nn]);
    }
    // load B (160x128 halves = 2560 uint4)
    #pragma unroll
    for (int m = 0; m < 10; ++m) {
        int e = (m << 8) + t;
        int row = e >> 4, col8 = (e & 15) << 3;
        *(uint4*)&sm->Bs[row][col8] = *(const uint4*)&g_Bh[row * 128 + col8];
    }
    __syncthreads();

    // emit fp16 transposed features (512 uint4)
    #pragma unroll
    for (int m = 0; m < 2; ++m) {
        int e = (m << 8) + t;
        int row = e >> 4, col8 = (e & 15) << 3;
        *(uint4*)&g_xsTh[(gbase + row) * 128 + col8] = *(const uint4*)&sm->As[row][col8];
    }

    // MMA: warp = (mt, ng): rows r0=mt*16, chans [ng*40, ng*40+40)
    const int mt = w & 1, ng = w >> 1;
    const int r0 = mt << 4;
    float c[5][4];
    #pragma unroll
    for (int nt = 0; nt < 5; ++nt)
        #pragma unroll
        for (int q = 0; q < 4; ++q) c[nt][q] = 0.f;

    #pragma unroll
    for (int ks = 0; ks < 8; ++ks) {
        int k0 = ks << 4;
        uint32_t A[4];
        const __half* ea = &sm->As[r0 + (lane & 15)][k0 + ((lane >> 4) << 3)];
        ldmatrix_x4(A, (uint32_t)__cvta_generic_to_shared(ea));
        #pragma unroll
        for (int nt = 0; nt < 5; ++nt) {
            uint32_t b0, b1v;
            const __half* wb = &sm->Bs[ng * 40 + (nt << 3) + (lane & 7)]
                                      [k0 + (((lane >> 3) & 1) << 3)];
            ldmatrix_x2(b0, b1v, (uint32_t)__cvta_generic_to_shared(wb));
            mma16816(c[nt], A, b0, b1v);
        }
    }

    // epilogue: D[pt][chan] + bias -> Qp / Qpp
    {
        const int pt = r0 + (lane >> 2);
        #pragma unroll
        for (int nt = 0; nt < 5; ++nt) {
            int chan = ng * 40 + (nt << 3) + ((lane & 3) << 1);
            if (chan < 128) {
                float bx = __ldg(&g_p0[chan]), by = __ldg(&g_p0[chan + 1]);
                *(float2*)&g_Qp[(gbase + pt) * 128 + chan] =
                    make_float2(c[nt][0] + bx, c[nt][1] + by);
                *(float2*)&g_Qp[(gbase + pt + 8) * 128 + chan] =
                    make_float2(c[nt][2] + bx, c[nt][3] + by);
            } else {
                int j = chan - 128;
                float bx = __ldg(&g_pq0[j]), by = __ldg(&g_pq0[j + 1]);
                *(float2*)&g_Qpp[(gbase + pt) * 32 + j] =
                    make_float2(c[nt][0] + bx, c[nt][1] + by);
                *(float2*)&g_Qpp[(gbase + pt + 8) * 32 + j] =
                    make_float2(c[nt][2] + bx, c[nt][3] + by);
            }
        }
    }
}

// ---------------- shared memory layout for main (~44KB) ----------------
struct __align__(16) SM {
    __half E[64][136];     // fp16 sin/cos embedding
    __half W1s[32][136];   // fp16 W1^T [j][d]
    float rh[64][34];      // relu hidden
    float Qp[4][128];
    float Qpp[4][32];
    float dp[64][4];
    float Bg[256];
    float vpart[8][128];
    float logit[64];
    float attn[64];
    float rden[4];
    float ctr[4][4];
    int   idx[64];
};

// ---------------- main kernel: 4 points/block ----------------
__global__ __launch_bounds__(THREADS, 4) void lsga_main_kernel(
    const float* __restrict__ coords, const void* __restrict__ idxp,
    const float* __restrict__ Bg, const float* __restrict__ b1) {

    extern __shared__ char smem_raw[];
    SM* sm = reinterpret_cast<SM*>(smem_raw);

    const int t = threadIdx.x;
    const int lane = t & 31;
    const int w = t >> 5;
    const int g0 = blockIdx.x * PTS;
    const int b = g0 >> 13;
    const int n0 = g0 & (NN - 1);
    const size_t base = (size_t)b * NN + n0;

    // ---- P0: loads ----
    #pragma unroll
    for (int m = 0; m < 2; ++m) {
        int e = (m << 8) + t;
        int p = e >> 7, c = e & 127;
        sm->Qp[p][c] = g_Qp[(base + p) * 128 + c];
    }
    if (t < 128) {
        int p = t >> 5, j = t & 31;
        sm->Qpp[p][j] = g_Qpp[(base + p) * 32 + j];
    }
    sm->Bg[t] = Bg[t] * TWO_PI;
    #pragma unroll
    for (int m = 0; m < 2; ++m) {
        int e = (m << 8) + t;
        int j = e >> 4, c0 = (e & 15) << 3;
        *(uint4*)&sm->W1s[j][c0] = *(const uint4*)&g_W1h[j * 128 + c0];
    }
    if (t < 64) {
        long long v;
        if (g_idx64) v = ((const long long*)idxp)[base * 16 + t];
        else         v = (long long)((const int*)idxp)[base * 16 + t];
        sm->idx[t] = (int)v;
    }
    if (t < 16) {
        int p = t >> 2, a = t & 3;
        sm->ctr[p][a] = coords[(base + p) * 4 + a];
    }
    __syncthreads();

    // ---- P1: delta-p + fp16 neighbor gather into registers ----
    {
        int r = t >> 2, a = t & 3, p = t >> 6;
        sm->dp[r][a] = coords[((size_t)b * NN + sm->idx[r]) * 4 + a] - sm->ctr[p][a];
    }
    float4 nbf[8];                         // rows 8w..8w+7, channels 4*lane..+3
    #pragma unroll
    for (int rr = 0; rr < 8; ++rr) {
        int r = (w << 3) + rr;
        uint2 hv = __ldg((const uint2*)(g_xsTh + ((size_t)b * NN + sm->idx[r]) * 128) + lane);
        __half2* hp = (__half2*)&hv;
        float2 f0 = __half22float2(hp[0]);
        float2 f1 = __half22float2(hp[1]);
        nbf[rr] = make_float4(f0.x, f0.y, f1.x, f1.y);
    }
    __syncthreads();

    // ---- P2: Fourier sincos -> fp16 E ----
    #pragma unroll
    for (int m = 0; m < 8; ++m) {
        int item = (m << 8) + t;
        int r = item >> 5, d = (item & 31) << 1;
        float pr0 = sm->dp[r][0] * sm->Bg[d]
                  + sm->dp[r][1] * sm->Bg[64 + d]
                  + sm->dp[r][2] * sm->Bg[128 + d]
                  + sm->dp[r][3] * sm->Bg[192 + d];
        float pr1 = sm->dp[r][0] * sm->Bg[d + 1]
                  + sm->dp[r][1] * sm->Bg[64 + d + 1]
                  + sm->dp[r][2] * sm->Bg[128 + d + 1]
                  + sm->dp[r][3] * sm->Bg[192 + d + 1];
        float s0, c0, s1, c1;
        __sincosf(pr0, &s0, &c0);
        __sincosf(pr1, &s1, &c1);
        *(half2*)&sm->E[r][d]      = __floats2half2_rn(s0, s1);
        *(half2*)&sm->E[r][64 + d] = __floats2half2_rn(c0, c1);
    }
    __syncthreads();

    // ---- P3: hidden MLP via tensor cores, m16 x n16 x k128 per warp ----
    {
        const int mtile = w & 3;
        const int nh = w >> 2;
        const int r0 = mtile << 4;
        const int jn0 = nh << 4;

        float c[2][4];
        #pragma unroll
        for (int nt = 0; nt < 2; ++nt)
            #pragma unroll
            for (int q = 0; q < 4; ++q) c[nt][q] = 0.f;

        #pragma unroll
        for (int ks = 0; ks < 8; ++ks) {
            int k0 = ks << 4;
            uint32_t A[4];
            const __half* ea = &sm->E[r0 + (lane & 15)][k0 + ((lane >> 4) << 3)];
            ldmatrix_x4(A, (uint32_t)__cvta_generic_to_shared(ea));
            #pragma unroll
            for (int nt = 0; nt < 2; ++nt) {
                uint32_t b0, b1v;
                const __half* wb = &sm->W1s[jn0 + (nt << 3) + (lane & 7)]
                                          [k0 + (((lane >> 3) & 1) << 3)];
                ldmatrix_x2(b0, b1v, (uint32_t)__cvta_generic_to_shared(wb));
                mma16816(c[nt], A, b0, b1v);
            }
        }

        const int row1 = r0 + (lane >> 2);
        #pragma unroll
        for (int nt = 0; nt < 2; ++nt) {
            int col = jn0 + (nt << 3) + ((lane & 3) << 1);
            float bb0 = __ldg(&b1[col]), bb1 = __ldg(&b1[col + 1]);
            *(float2*)&sm->rh[row1][col] =
                make_float2(fmaxf(c[nt][0] + bb0, 0.f), fmaxf(c[nt][1] + bb1, 0.f));
            *(float2*)&sm->rh[row1 + 8][col] =
                make_float2(fmaxf(c[nt][2] + bb0, 0.f), fmaxf(c[nt][3] + bb1, 0.f));
        }
    }
    __syncthreads();

    // ---- P5: logits ----
    {
        const int p = w >> 1;
        float4 qp4 = *(const float4*)&sm->Qp[p][lane << 2];
        float qpp = sm->Qpp[p][lane];
        #pragma unroll
        for (int rr = 0; rr < 8; ++rr) {
            int r = (w << 3) + rr;
            float val = qp4.x * nbf[rr].x + qp4.y * nbf[rr].y
                      + qp4.z * nbf[rr].z + qp4.w * nbf[rr].w
                      + sm->rh[r][lane] * qpp;
            #pragma unroll
            for (int off = 16; off; off >>= 1)
                val += __shfl_xor_sync(0xffffffffu, val, off);
            if (lane == 0) sm->logit[r] = val * RSQRT_C;
        }
    }
    __syncthreads();

    // ---- P6: softmax ----
    if (t < 64) {
        int p = t >> 4, k = t & 15;
        float lg = sm->logit[t];
        float mx = lg;
        #pragma unroll
        for (int off = 8; off; off >>= 1)
            mx = fmaxf(mx, __shfl_xor_sync(0xffffffffu, mx, off));
        float e = __expf(lg - mx);
        float s = e;
        #pragma unroll
        for (int off = 8; off; off >>= 1)
            s += __shfl_xor_sync(0xffffffffu, s, off);
        sm->attn[t] = e;
        if (k == 0) sm->rden[p] = 1.0f / s;
    }
    __syncthreads();

    // ---- P7: aggregates -> g_vh (fp16) ----
    {
        float4 fa = make_float4(0.f, 0.f, 0.f, 0.f);
        #pragma unroll
        for (int rr = 0; rr < 8; ++rr) {
            float a = sm->attn[(w << 3) + rr];
            fa.x = fmaf(a, nbf[rr].x, fa.x);
            fa.y = fmaf(a, nbf[rr].y, fa.y);
            fa.z = fmaf(a, nbf[rr].z, fa.z);
            fa.w = fmaf(a, nbf[rr].w, fa.w);
        }
        *(float4*)&sm->vpart[w][lane << 2] = fa;
    }
    if (t < 128) {
        int p = t >> 5, j = t & 31;
        float ha = 0.f;
        #pragma unroll
        for (int k = 0; k < 16; ++k)
            ha = fmaf(sm->attn[p * 16 + k], sm->rh[p * 16 + k][j], ha);
        g_vh[(base + p) * 160 + 128 + j] = __float2half(ha * sm->rden[p]);
    }
    __syncthreads();

    #pragma unroll
    for (int m = 0; m < 2; ++m) {
        int e = (m << 8) + t;
        int p = e >> 7, c = e & 127;
        g_vh[(base + p) * 160 + c] =
            __float2half((sm->vpart[2 * p][c] + sm->vpart[2 * p + 1][c]) * sm->rden[p]);
    }
}

// ---------------- out kernel: tensor GEMM m32 x n128 x k160 + transpose ----
struct __align__(16) SMOUT {
    __half As[32][168];    // v [pt][i], 336B row stride
    __half Bs[128][168];   // Wfused [o][i]
    float  os[128][34];    // out transposed [chan][pt]
};
__global__ __launch_bounds__(256) void out_kernel(float* __restrict__ out) {
    extern __shared__ char smem_raw[];
    SMOUT* sm = reinterpret_cast<SMOUT*>(smem_raw);
    const int t = threadIdx.x;
    const int lane = t & 31, w = t >> 5;
    const int blk = blockIdx.x;
    const int b = blk >> 8;
    const int n0 = (blk & 255) << 5;
    const size_t gbase = (size_t)b * NN + n0;

    // load A: 32x160 halves = 640 uint4
    #pragma unroll
    for (int m = 0; m < 3; ++m) {
        int e = (m << 8) + t;
        if (e < 640) {
            int row = e / 20, col8 = (e % 20) << 3;
            *(uint4*)&sm->As[row][col8] = *(const uint4*)&g_vh[(gbase + row) * 160 + col8];
        }
    }
    // load B: 128x160 halves = 2560 uint4
    #pragma unroll
    for (int m = 0; m < 10; ++m) {
        int e = (m << 8) + t;
        int row = e / 20, col8 = (e % 20) << 3;
        *(uint4*)&sm->Bs[row][col8] = *(const uint4*)&g_Wcath[row * 160 + col8];
    }
    __syncthreads();

    // MMA: warp = (mt, ng): rows r0=mt*16, chans [ng*32, ng*32+32)
    const int mt = w & 1, ng = w >> 1;
    const int r0 = mt << 4;
    float c[4][4];
    #pragma unroll
    for (int nt = 0; nt < 4; ++nt)
        #pragma unroll
        for (int q = 0; q < 4; ++q) c[nt][q] = 0.f;

    #pragma unroll
    for (int ks = 0; ks < 10; ++ks) {
        int k0 = ks << 4;
        uint32_t A[4];
        const __half* ea = &sm->As[r0 + (lane & 15)][k0 + ((lane >> 4) << 3)];
        ldmatrix_x4(A, (uint32_t)__cvta_generic_to_shared(ea));
        #pragma unroll
        for (int nt = 0; nt < 4; ++nt) {
            uint32_t b0, b1v;
            const __half* wb = &sm->Bs[(ng << 5) + (nt << 3) + (lane & 7)]
                                      [k0 + (((lane >> 3) & 1) << 3)];
            ldmatrix_x2(b0, b1v, (uint32_t)__cvta_generic_to_shared(wb));
            mma16816(c[nt], A, b0, b1v);
        }
    }

    // epilogue: bias + transpose into os
    {
        const int pt = r0 + (lane >> 2);
        #pragma unroll
        for (int nt = 0; nt < 4; ++nt) {
            int chan = (ng << 5) + (nt << 3) + ((lane & 3) << 1);
            float bx = __ldg(&g_b3[chan]), by = __ldg(&g_b3[chan + 1]);
            sm->os[chan][pt]         = c[nt][0] + bx;
            sm->os[chan + 1][pt]     = c[nt][1] + by;
            sm->os[chan][pt + 8]     = c[nt][2] + bx;
            sm->os[chan + 1][pt + 8] = c[nt][3] + by;
        }
    }
    __syncthreads();

    // coalesced store [C, N]
    #pragma unroll
    for (int m = 0; m < 16; ++m) {
        int e = (m << 8) + t;
        int chan = e >> 5, pt = e & 31;
        out[((size_t)(b * 128 + chan) << 13) + n0 + pt] = sm->os[chan][pt];
    }
}

// ---------------- launch ----------------
extern "C" void kernel_launch(void* const* d_in, const int* in_sizes, int n_in,
                              void* d_out, int out_size) {
    const float* x      = (const float*)d_in[0];
    const float* coords = (const float*)d_in[1];
    const void*  idx    = d_in[2];
    const float* Bg     = (const float*)d_in[3];
    const float* W1     = (const float*)d_in[4];
    const float* b1     = (const float*)d_in[5];
    const float* W2     = (const float*)d_in[6];
    const float* b2     = (const float*)d_in[7];
    const float* Wq     = (const float*)d_in[8];
    const float* bq     = (const float*)d_in[9];
    const float* Wk     = (const float*)d_in[10];
    const float* Wv     = (const float*)d_in[12];
    const float* bv     = (const float*)d_in[13];
    const float* Wo     = (const float*)d_in[14];
    const float* bo     = (const float*)d_in[15];
    float* out = (float*)d_out;

    static bool attr_set = false;
    if (!attr_set) {
        cudaFuncSetAttribute(lsga_main_kernel,
                             cudaFuncAttributeMaxDynamicSharedMemorySize, (int)sizeof(SM));
        cudaFuncSetAttribute(pre_kernel,
                             cudaFuncAttributeMaxDynamicSharedMemorySize, (int)sizeof(SMPRE));
        cudaFuncSetAttribute(out_kernel,
                             cudaFuncAttributeMaxDynamicSharedMemorySize, (int)sizeof(SMOUT));
        attr_set = true;
    }

    prep1_kernel<<<129, 128>>>(Wq, Wk, Wv, Wo, bq, (const int*)idx);
    prep2_kernel<<<128, 128>>>(W2, Wo, b2, bv, bo, W1);
    pre_kernel<<<(BB * NN) / 32, 256, sizeof(SMPRE)>>>(x);
    lsga_main_kernel<<<(BB * NN) / PTS, THREADS, sizeof(SM)>>>(coords, idx, Bg, b1);
    out_kernel<<<(BB * NN) / 32, 256, sizeof(SMOUT)>>>(out);
}